// round 1
// baseline (speedup 1.0000x reference)
#include <cuda_runtime.h>
#include <cstdint>
#include <math.h>

// ---------------- problem constants ----------------
#define NF      16381      // number of frames
#define TS      8388608    // total samples
#define FFTLEN  2048
#define HOP     512
#define NBINS   84
#define FB      1025       // freq bins (fftLen/2+1)

typedef unsigned long long ull;

// ---------------- packed f32x2 helpers ----------------
__device__ __forceinline__ ull pk(float x, float y) {
    ull r; asm("mov.b64 %0, {%1,%2};" : "=l"(r) : "f"(x), "f"(y)); return r;
}
__device__ __forceinline__ float2 upk(ull v) {
    float2 r; asm("mov.b64 {%0,%1}, %2;" : "=f"(r.x), "=f"(r.y) : "l"(v)); return r;
}
__device__ __forceinline__ void fma2(ull &d, ull a, ull b) {
    asm("fma.rn.f32x2 %0, %1, %2, %0;" : "+l"(d) : "l"(a), "l"(b));
}

// Collapsed CQT kernels: g_W[0][k][n] = Wr, g_W[1][k][n] = Wi
__device__ float g_W[2 * NBINS * FFTLEN];

// ======================================================================
// Kernel 1: combine  W = (kr + j*ki) applied to (wcos, wsin)
//   Wr[k,n] = sum_b kr[k,b]*wcos[b,n] - ki[k,b]*wsin[b,n]
//   Wi[k,n] = sum_b kr[k,b]*wsin[b,n] + ki[k,b]*wcos[b,n]
// grid (8, 14): 8 n-groups of 256, 14 k-groups of 6 bins. 256 threads.
// b packed in pairs for f32x2; split accumulators avoid negation in loop.
// ======================================================================
__global__ __launch_bounds__(256) void cqt_combine_kernel(
    const float* __restrict__ kr, const float* __restrict__ ki,
    const float* __restrict__ wcos, const float* __restrict__ wsin)
{
    __shared__ float sb[2][6][258];   // kr/ki chunk, even stride for float2
    const int tid = threadIdx.x;
    const int n  = blockIdx.x * 256 + tid;
    const int k0 = blockIdx.y * 6;

    ull A[6], B[6], C[6], D[6];
    #pragma unroll
    for (int kk = 0; kk < 6; kk++) { A[kk] = B[kk] = C[kk] = D[kk] = 0ull; }

    for (int c = 0; c < 4; c++) {           // b in chunks of 256 (0..1023)
        const int bb = c * 256;
        __syncthreads();
        #pragma unroll
        for (int it = 0; it < 6; it++) {    // stage kr/ki chunk (smem)
            const int kk = it;
            sb[0][kk][tid] = kr[(k0 + kk) * FB + bb + tid];
            sb[1][kk][tid] = ki[(k0 + kk) * FB + bb + tid];
        }
        __syncthreads();
        #pragma unroll 4
        for (int b = 0; b < 256; b += 2) {
            const float* wcp = wcos + (bb + b) * FFTLEN + n;
            const float* wsp = wsin + (bb + b) * FFTLEN + n;
            const ull wc = pk(wcp[0], wcp[FFTLEN]);
            const ull ws = pk(wsp[0], wsp[FFTLEN]);
            #pragma unroll
            for (int kk = 0; kk < 6; kk++) {
                float2 r2 = *(const float2*)&sb[0][kk][b];
                float2 i2 = *(const float2*)&sb[1][kk][b];
                ull kr2 = pk(r2.x, r2.y);
                ull ki2 = pk(i2.x, i2.y);
                fma2(A[kk], kr2, wc);
                fma2(B[kk], ki2, ws);
                fma2(C[kk], kr2, ws);
                fma2(D[kk], ki2, wc);
            }
        }
    }
    // tail b = 1024
    const float wc0 = wcos[1024 * FFTLEN + n];
    const float ws0 = wsin[1024 * FFTLEN + n];
    #pragma unroll
    for (int kk = 0; kk < 6; kk++) {
        const int k = k0 + kk;
        const float r = kr[k * FB + 1024];
        const float i = ki[k * FB + 1024];
        float2 a = upk(A[kk]), b2 = upk(B[kk]), cc = upk(C[kk]), dd = upk(D[kk]);
        const float Wr = (a.x + a.y) - (b2.x + b2.y) + (r * wc0 - i * ws0);
        const float Wi = (cc.x + cc.y) + (dd.x + dd.y) + (r * ws0 + i * wc0);
        g_W[k * FFTLEN + n]                     = Wr;
        g_W[(NBINS + k) * FFTLEN + n]           = Wi;
    }
}

// ======================================================================
// Kernel 2: main strided gemm + magnitude
//   out[k,f] = sqrt( (sum_n Wr[k,n] x[512f+n])^2 + (sum_n Wi[k,n] x[512f+n])^2 )
// Block: 512 threads = 16 f-threads x 32 k-groups; tile = 64 frames x 96 bins
// (bins padded 84->96, pad rows staged as zero). n chunked by 32 through smem.
// f32x2 lanes packed over n -> no splat overhead; horizontal add in epilogue.
// ======================================================================
#define BF   64
#define NCH  32
#define MT   512

__global__ __launch_bounds__(MT, 1) void cqt_main_kernel(
    const float* __restrict__ x, float* __restrict__ out)
{
    __shared__ float Ws[2][96][NCH + 2];   // even row stride 34
    __shared__ float xs[BF][NCH + 2];

    const int tid  = threadIdx.x;
    const int fx   = tid & 15;        // f-thread within warp
    const int kg   = tid >> 4;        // 0..31 k-group
    const int bin0 = kg * 3;
    const int f0   = blockIdx.x * BF;

    ull acc[3][4][2];
    #pragma unroll
    for (int i = 0; i < 3; i++)
        #pragma unroll
        for (int j = 0; j < 4; j++) { acc[i][j][0] = 0ull; acc[i][j][1] = 0ull; }

    for (int nc = 0; nc < FFTLEN; nc += NCH) {
        __syncthreads();   // previous compute done before restage
        // stage W chunk: 192 rows x 32 cols
        for (int idx = tid; idx < 192 * NCH; idx += MT) {
            const int rr = idx >> 5;          // 0..191 (p*96 + r)
            const int nn = idx & (NCH - 1);
            const int p  = rr / 96;
            const int r  = rr - p * 96;
            float v = 0.f;
            if (r < NBINS) v = g_W[p * (NBINS * FFTLEN) + r * FFTLEN + nc + nn];
            Ws[p][r][nn] = v;
        }
        // stage x chunk: 64 frames x 32 samples (float2 granularity)
        for (int idx = tid; idx < BF * (NCH / 2); idx += MT) {
            const int fr = idx >> 4;
            const int n2 = (idx & 15) * 2;
            const int f  = f0 + fr;
            float2 v = make_float2(0.f, 0.f);
            if (f < NF) v = *(const float2*)&x[f * HOP + nc + n2];
            *(float2*)&xs[fr][n2] = v;
        }
        __syncthreads();

        #pragma unroll 8
        for (int n2 = 0; n2 < NCH; n2 += 2) {
            ull w[3][2];
            #pragma unroll
            for (int i = 0; i < 3; i++) {
                float2 t0 = *(const float2*)&Ws[0][bin0 + i][n2];
                float2 t1 = *(const float2*)&Ws[1][bin0 + i][n2];
                w[i][0] = pk(t0.x, t0.y);
                w[i][1] = pk(t1.x, t1.y);
            }
            ull xv[4];
            #pragma unroll
            for (int j = 0; j < 4; j++) {
                float2 t = *(const float2*)&xs[fx + 16 * j][n2];
                xv[j] = pk(t.x, t.y);
            }
            #pragma unroll
            for (int i = 0; i < 3; i++)
                #pragma unroll
                for (int j = 0; j < 4; j++) {
                    fma2(acc[i][j][0], w[i][0], xv[j]);
                    fma2(acc[i][j][1], w[i][1], xv[j]);
                }
        }
    }

    // epilogue: horizontal add + magnitude
    #pragma unroll
    for (int i = 0; i < 3; i++) {
        const int bin = bin0 + i;
        #pragma unroll
        for (int j = 0; j < 4; j++) {
            const int f = f0 + fx + 16 * j;
            if (bin < NBINS && f < NF) {
                float2 r2 = upk(acc[i][j][0]);
                float2 q2 = upk(acc[i][j][1]);
                const float re = r2.x + r2.y;
                const float im = q2.x + q2.y;
                out[bin * NF + f] = sqrtf(re * re + im * im);
            }
        }
    }
}

// ======================================================================
extern "C" void kernel_launch(void* const* d_in, const int* in_sizes, int n_in,
                              void* d_out, int out_size) {
    const float* x    = (const float*)d_in[0];
    const float* wcos = (const float*)d_in[1];
    const float* wsin = (const float*)d_in[2];
    const float* kr   = (const float*)d_in[3];
    const float* ki   = (const float*)d_in[4];
    float* out = (float*)d_out;

    cqt_combine_kernel<<<dim3(8, 14), 256>>>(kr, ki, wcos, wsin);
    cqt_main_kernel<<<(NF + BF - 1) / BF, MT>>>(x, out);
}

// round 3
// speedup vs baseline: 2.4616x; 2.4616x over previous
#include <cuda_runtime.h>
#include <cuda_bf16.h>
#include <cuda.h>
#include <cstdint>
#include <math.h>

// ---------------- problem constants ----------------
#define NF      16381
#define TS      8388608
#define XPAD    8390144      // 512*16387
#define FFTLEN  2048
#define HOP     512
#define NBINS   84
#define FB      1025
#define NTC     192          // padded N (2*84 -> 192)
#define KC      32           // K chunk (32 bf16 = 64B rows, SW64)
#define NCHUNK  (FFTLEN / KC)   // 64
#define TILE_M  64
#define GRID_M  256          // 16384 / 64
#define NSTAGE  3

typedef unsigned long long ull;
typedef __nv_bfloat16 bf16;

// ---------------- scratch ----------------
__device__ bf16 g_xh[XPAD];
__device__ bf16 g_xl[XPAD];
__device__ bf16 g_Wh[NTC * FFTLEN];
__device__ bf16 g_Wl[NTC * FFTLEN];

// ---------------- packed f32x2 helpers (combine kernel) ----------------
__device__ __forceinline__ ull pk(float x, float y) {
    ull r; asm("mov.b64 %0, {%1,%2};" : "=l"(r) : "f"(x), "f"(y)); return r;
}
__device__ __forceinline__ float2 upk(ull v) {
    float2 r; asm("mov.b64 {%0,%1}, %2;" : "=f"(r.x), "=f"(r.y) : "l"(v)); return r;
}
__device__ __forceinline__ void fma2(ull &d, ull a, ull b) {
    asm("fma.rn.f32x2 %0, %1, %2, %0;" : "+l"(d) : "l"(a), "l"(b));
}

// ---------------- base-ISA PTX helpers ----------------
__device__ __forceinline__ uint32_t smem_u32(const void* p) {
    uint32_t a;
    asm("{ .reg .u64 t; cvta.to.shared.u64 t, %1; cvt.u32.u64 %0, t; }" : "=r"(a) : "l"(p));
    return a;
}

#define MBAR_INIT(addr, cnt) \
    asm volatile("mbarrier.init.shared.b64 [%0], %1;" :: "r"((uint32_t)(addr)), "r"((uint32_t)(cnt)) : "memory")
#define MBAR_INVAL(addr) \
    asm volatile("mbarrier.inval.shared.b64 [%0];" :: "r"((uint32_t)(addr)) : "memory")
#define MBAR_ARRIVE(addr) \
    asm volatile("mbarrier.arrive.shared.b64 _, [%0];" :: "r"((uint32_t)(addr)) : "memory")
#define MBAR_EXPECT_TX(addr, bytes) \
    asm volatile("mbarrier.arrive.expect_tx.shared.b64 _, [%0], %1;" \
        :: "r"((uint32_t)(addr)), "r"((uint32_t)(bytes)) : "memory")

#define WAITP(mbar, ph) do { \
    uint32_t _m = (uint32_t)(mbar); uint32_t _p = (uint32_t)(ph); uint32_t _d; \
    asm volatile("{\n\t.reg .pred p;\n\t" \
        "mbarrier.try_wait.parity.acquire.cta.shared::cta.b64 p, [%1], %2;\n\t" \
        "selp.b32 %0, 1, 0, p;\n\t}" : "=r"(_d) : "r"(_m), "r"(_p) : "memory"); \
    if (!_d) { \
        asm volatile("{\n\t.reg .pred P1;\n\t" \
            "WL_%=:\n\t" \
            "mbarrier.try_wait.parity.acquire.cta.shared::cta.b64 P1, [%0], %1, 0x989680;\n\t" \
            "@P1 bra.uni WD_%=;\n\t" \
            "bra.uni WL_%=;\n\t" \
            "WD_%=:\n\t}" :: "r"(_m), "r"(_p) : "memory"); \
    } } while (0)

#define TMA2D(dst, map, x0, y0, mb) \
    asm volatile("cp.async.bulk.tensor.2d.shared::cta.global.tile.mbarrier::complete_tx::bytes " \
        "[%0], [%1, {%2, %3}], [%4];" \
        :: "r"((uint32_t)(dst)), "l"(map), "r"((int)(x0)), "r"((int)(y0)), "r"((uint32_t)(mb)) : "memory")

__device__ __forceinline__ void ldsm4(uint32_t* r, uint32_t addr) {
    asm volatile("ldmatrix.sync.aligned.m8n8.x4.shared.b16 {%0,%1,%2,%3}, [%4];"
        : "=r"(r[0]), "=r"(r[1]), "=r"(r[2]), "=r"(r[3]) : "r"(addr));
}
__device__ __forceinline__ void mma_bf16(float* c, const uint32_t* a, const uint32_t* b) {
    asm volatile("mma.sync.aligned.m16n8k16.row.col.f32.bf16.bf16.f32 "
        "{%0,%1,%2,%3}, {%4,%5,%6,%7}, {%8,%9}, {%0,%1,%2,%3};"
        : "+f"(c[0]), "+f"(c[1]), "+f"(c[2]), "+f"(c[3])
        : "r"(a[0]), "r"(a[1]), "r"(a[2]), "r"(a[3]), "r"(b[0]), "r"(b[1]));
}

// ======================================================================
// Kernel 1: combine  W = (kr + j*ki) applied to (wcos, wsin), bf16 hi/lo
// ======================================================================
__global__ __launch_bounds__(256) void cqt_combine_kernel(
    const float* __restrict__ kr, const float* __restrict__ ki,
    const float* __restrict__ wcos, const float* __restrict__ wsin)
{
    __shared__ float sb[2][6][258];
    const int tid = threadIdx.x;
    const int n  = blockIdx.x * 256 + tid;
    const int k0 = blockIdx.y * 6;

    ull A[6], B[6], C[6], D[6];
    #pragma unroll
    for (int kk = 0; kk < 6; kk++) { A[kk] = B[kk] = C[kk] = D[kk] = 0ull; }

    for (int c = 0; c < 4; c++) {
        const int bb = c * 256;
        __syncthreads();
        #pragma unroll
        for (int kk = 0; kk < 6; kk++) {
            sb[0][kk][tid] = kr[(k0 + kk) * FB + bb + tid];
            sb[1][kk][tid] = ki[(k0 + kk) * FB + bb + tid];
        }
        __syncthreads();
        #pragma unroll 4
        for (int b = 0; b < 256; b += 2) {
            const float* wcp = wcos + (bb + b) * FFTLEN + n;
            const float* wsp = wsin + (bb + b) * FFTLEN + n;
            const ull wc = pk(wcp[0], wcp[FFTLEN]);
            const ull ws = pk(wsp[0], wsp[FFTLEN]);
            #pragma unroll
            for (int kk = 0; kk < 6; kk++) {
                float2 r2 = *(const float2*)&sb[0][kk][b];
                float2 i2 = *(const float2*)&sb[1][kk][b];
                ull kr2 = pk(r2.x, r2.y);
                ull ki2 = pk(i2.x, i2.y);
                fma2(A[kk], kr2, wc);
                fma2(B[kk], ki2, ws);
                fma2(C[kk], kr2, ws);
                fma2(D[kk], ki2, wc);
            }
        }
    }
    const float wc0 = wcos[1024 * FFTLEN + n];
    const float ws0 = wsin[1024 * FFTLEN + n];
    #pragma unroll
    for (int kk = 0; kk < 6; kk++) {
        const int k = k0 + kk;
        const float r = kr[k * FB + 1024];
        const float i = ki[k * FB + 1024];
        float2 a = upk(A[kk]), b2 = upk(B[kk]), cc = upk(C[kk]), dd = upk(D[kk]);
        const float Wr = (a.x + a.y) - (b2.x + b2.y) + (r * wc0 - i * ws0);
        const float Wi = (cc.x + cc.y) + (dd.x + dd.y) + (r * ws0 + i * wc0);
        bf16 h;
        h = __float2bfloat16(Wr);
        g_Wh[k * FFTLEN + n] = h;
        g_Wl[k * FFTLEN + n] = __float2bfloat16(Wr - __bfloat162float(h));
        h = __float2bfloat16(Wi);
        g_Wh[(NBINS + k) * FFTLEN + n] = h;
        g_Wl[(NBINS + k) * FFTLEN + n] = __float2bfloat16(Wi - __bfloat162float(h));
    }
}

// ======================================================================
// Kernel 2: zero the W pad rows (168..191)
// ======================================================================
__global__ void wpad_kernel() {
    int i = blockIdx.x * 256 + threadIdx.x;
    if (i < (NTC - 2 * NBINS) * FFTLEN) {
        g_Wh[2 * NBINS * FFTLEN + i] = __float2bfloat16(0.f);
        g_Wl[2 * NBINS * FFTLEN + i] = __float2bfloat16(0.f);
    }
}

// ======================================================================
// Kernel 3: split x into bf16 hi/lo (zero pad to XPAD)
// ======================================================================
__global__ __launch_bounds__(256) void xsplit_kernel(const float* __restrict__ x) {
    int i = (blockIdx.x * 256 + threadIdx.x) * 4;
    if (i >= XPAD) return;
    float v[4];
    if (i + 4 <= TS) {
        float4 t = *(const float4*)(x + i);
        v[0] = t.x; v[1] = t.y; v[2] = t.z; v[3] = t.w;
    } else {
        #pragma unroll
        for (int j = 0; j < 4; j++) v[j] = (i + j < TS) ? x[i + j] : 0.f;
    }
    union { bf16 b[4]; uint2 u; } H, L;
    #pragma unroll
    for (int j = 0; j < 4; j++) {
        bf16 h = __float2bfloat16(v[j]);
        H.b[j] = h;
        L.b[j] = __float2bfloat16(v[j] - __bfloat162float(h));
    }
    *(uint2*)&g_xh[i] = H.u;
    *(uint2*)&g_xl[i] = L.u;
}

// ======================================================================
// Kernel 4: HMMA GEMM + magnitude epilogue
//   C[f, n] = sum_k frames[f,k] * W[n,k]  (3x bf16 split products)
// ======================================================================
// smem: [0..48) mbarriers; stages at 1024, each 32KB:
//   Ah 0 | Al 4096 | Bh 8192 | Bl 20480
#define STAGE_SZ   32768
#define STAGE0     1024
#define SMEM_TOTAL (STAGE0 + NSTAGE * STAGE_SZ)   // 99328
#define CHUNK_BYTES 32768

__device__ __forceinline__ void issue_chunk(
    uint32_t sb, int s, int f0, int c,
    const void* tXh, const void* tXl, const void* tWh, const void* tWl)
{
    const uint32_t mb = sb + s * 16;
    const uint32_t st = sb + STAGE0 + s * STAGE_SZ;
    const int kx = (c & 15) * 32;        // inner offset within 512
    const int ky = f0 + (c >> 4);        // row = frame + k/512
    MBAR_EXPECT_TX(mb, CHUNK_BYTES);
    TMA2D(st,         tXh, kx, ky, mb);
    TMA2D(st + 4096,  tXl, kx, ky, mb);
    TMA2D(st + 8192,  tWh, c * 32, 0, mb);
    TMA2D(st + 20480, tWl, c * 32, 0, mb);
}

__global__ __launch_bounds__(256, 2) void cqt_mma_kernel(
    const __grid_constant__ CUtensorMap tmXh,
    const __grid_constant__ CUtensorMap tmXl,
    const __grid_constant__ CUtensorMap tmWh,
    const __grid_constant__ CUtensorMap tmWl,
    float* __restrict__ out)
{
    extern __shared__ __align__(1024) char smem[];
    const uint32_t sb = smem_u32(smem);
    const int tid  = threadIdx.x;
    const int wid  = tid >> 5;
    const int lane = tid & 31;
    const int wm   = wid & 1;        // 2 m-warps
    const int wn   = wid >> 1;       // 4 n-warps
    const int f0   = blockIdx.x * TILE_M;

    // per-lane ldmatrix geometry (SW64 swizzle: off ^ ((off>>3)&0x30))
    const int arow  = wm * 32 + (lane & 15);
    const int akb   = (lane >> 4) * 16;            // 0 or 16
    const int aswz  = ((arow >> 1) & 3) << 4;
    const int abase = arow * 64;
    const int brown = (lane & 7) + ((lane & 16) ? 8 : 0);
    const int bkb   = (lane & 8) ? 16 : 0;
    const int bswz  = ((brown >> 1) & 3) << 4;
    const int bbase = (wn * 48 + brown) * 64;

    if (tid == 0) {
        #pragma unroll
        for (int s = 0; s < NSTAGE; s++) {
            MBAR_INIT(sb + s * 16, 1);        // full (tx-based)
            MBAR_INIT(sb + s * 16 + 8, 256);  // empty
        }
    }
    __syncthreads();

    if (tid == 0) {
        #pragma unroll
        for (int s = 0; s < NSTAGE; s++)
            issue_chunk(sb, s, f0, s, &tmXh, &tmXl, &tmWh, &tmWl);
    }

    float acc[2][6][4];
    #pragma unroll
    for (int t = 0; t < 2; t++)
        #pragma unroll
        for (int j = 0; j < 6; j++)
            #pragma unroll
            for (int q = 0; q < 4; q++) acc[t][j][q] = 0.f;

    int fph[NSTAGE] = {0, 0, 0};
    int eph[NSTAGE] = {0, 0, 0};

    for (int c = 0; c < NCHUNK; ++c) {
        const int s = c % NSTAGE;
        WAITP(sb + s * 16, fph[s]); fph[s] ^= 1;
        const uint32_t st = sb + STAGE0 + s * STAGE_SZ;

        #pragma unroll
        for (int ks = 0; ks < 2; ++ks) {
            uint32_t ah[2][4], alr[2][4], bh[6][2], blr[6][2];
            #pragma unroll
            for (int t = 0; t < 2; ++t) {
                const uint32_t ao = abase + t * 1024 + ((ks * 32 + akb) ^ aswz);
                ldsm4(ah[t],  st + ao);
                ldsm4(alr[t], st + 4096 + ao);
            }
            #pragma unroll
            for (int j2 = 0; j2 < 3; ++j2) {
                const uint32_t bo = bbase + j2 * 1024 + ((ks * 32 + bkb) ^ bswz);
                uint32_t r4[4];
                ldsm4(r4, st + 8192 + bo);
                bh[2*j2][0] = r4[0]; bh[2*j2][1] = r4[1];
                bh[2*j2+1][0] = r4[2]; bh[2*j2+1][1] = r4[3];
                ldsm4(r4, st + 20480 + bo);
                blr[2*j2][0] = r4[0]; blr[2*j2][1] = r4[1];
                blr[2*j2+1][0] = r4[2]; blr[2*j2+1][1] = r4[3];
            }
            #pragma unroll
            for (int t = 0; t < 2; ++t)
                #pragma unroll
                for (int j = 0; j < 6; ++j) {
                    mma_bf16(acc[t][j], ah[t],  bh[j]);
                    mma_bf16(acc[t][j], ah[t],  blr[j]);
                    mma_bf16(acc[t][j], alr[t], bh[j]);
                }
        }

        MBAR_ARRIVE(sb + s * 16 + 8);
        if (tid == 0 && c + NSTAGE < NCHUNK) {
            WAITP(sb + s * 16 + 8, eph[s]); eph[s] ^= 1;
            issue_chunk(sb, s, f0, c + NSTAGE, &tmXh, &tmXl, &tmWh, &tmWl);
        }
    }

    // ---------------- epilogue ----------------
    __syncthreads();
    float* Cs = (float*)(smem + STAGE0);   // [192][68]
    const int g  = lane >> 2;
    const int tc = lane & 3;
    #pragma unroll
    for (int t = 0; t < 2; ++t) {
        const int r0 = wm * 32 + t * 16 + g;
        #pragma unroll
        for (int j = 0; j < 6; ++j) {
            const int col = wn * 48 + j * 8 + tc * 2;
            Cs[col * 68 + r0]           = acc[t][j][0];
            Cs[(col + 1) * 68 + r0]     = acc[t][j][1];
            Cs[col * 68 + r0 + 8]       = acc[t][j][2];
            Cs[(col + 1) * 68 + r0 + 8] = acc[t][j][3];
        }
    }
    __syncthreads();
    #pragma unroll
    for (int i = tid; i < NBINS * TILE_M; i += 256) {
        const int bin = i >> 6;
        const int r   = i & 63;
        const int f   = f0 + r;
        if (f < NF) {
            const float re = Cs[bin * 68 + r];
            const float im = Cs[(bin + NBINS) * 68 + r];
            out[bin * NF + f] = sqrtf(re * re + im * im);
        }
    }

    __syncthreads();
    if (tid == 0) {
        #pragma unroll
        for (int s = 0; s < NSTAGE; s++) {
            MBAR_INVAL(sb + s * 16);
            MBAR_INVAL(sb + s * 16 + 8);
        }
    }
}

// ======================================================================
// host side
// ======================================================================
typedef CUresult (CUDAAPI *EncodeFn)(
    CUtensorMap*, CUtensorMapDataType, cuuint32_t, void*,
    const cuuint64_t*, const cuuint64_t*, const cuuint32_t*, const cuuint32_t*,
    CUtensorMapInterleave, CUtensorMapSwizzle, CUtensorMapL2promotion,
    CUtensorMapFloatOOBfill);

static void encode_2d(EncodeFn enc, CUtensorMap* tm, void* ptr,
                      unsigned long long d0, unsigned long long d1,
                      unsigned long long strideB,
                      unsigned box0, unsigned box1) {
    cuuint64_t dims[2] = {d0, d1};
    cuuint64_t str[1]  = {strideB};
    cuuint32_t box[2]  = {box0, box1};
    cuuint32_t es[2]   = {1, 1};
    enc(tm, CU_TENSOR_MAP_DATA_TYPE_BFLOAT16, 2, ptr, dims, str, box, es,
        CU_TENSOR_MAP_INTERLEAVE_NONE, CU_TENSOR_MAP_SWIZZLE_64B,
        CU_TENSOR_MAP_L2_PROMOTION_L2_128B, CU_TENSOR_MAP_FLOAT_OOB_FILL_NONE);
}

extern "C" void kernel_launch(void* const* d_in, const int* in_sizes, int n_in,
                              void* d_out, int out_size) {
    const float* x    = (const float*)d_in[0];
    const float* wcos = (const float*)d_in[1];
    const float* wsin = (const float*)d_in[2];
    const float* kr   = (const float*)d_in[3];
    const float* ki   = (const float*)d_in[4];
    float* out = (float*)d_out;

    // driver entry point without -lcuda link dependency
    void* fn = nullptr;
    cudaDriverEntryPointQueryResult st;
#if CUDART_VERSION >= 12050
    cudaGetDriverEntryPointByVersion("cuTensorMapEncodeTiled", &fn, 12000,
                                     cudaEnableDefault, &st);
#else
    cudaGetDriverEntryPoint("cuTensorMapEncodeTiled", &fn, cudaEnableDefault, &st);
#endif
    EncodeFn enc = (EncodeFn)fn;

    void *pxh, *pxl, *pwh, *pwl;
    cudaGetSymbolAddress(&pxh, g_xh);
    cudaGetSymbolAddress(&pxl, g_xl);
    cudaGetSymbolAddress(&pwh, g_Wh);
    cudaGetSymbolAddress(&pwl, g_Wl);

    CUtensorMap tmXh, tmXl, tmWh, tmWl;
    // x viewed as [inner 512, rows 16387], stride 1024B, box [32, 64]
    encode_2d(enc, &tmXh, pxh, 512, 16387, 512ull * sizeof(bf16), 32, TILE_M);
    encode_2d(enc, &tmXl, pxl, 512, 16387, 512ull * sizeof(bf16), 32, TILE_M);
    // W: [2048, 192], stride 4096B, box [32, 192]
    encode_2d(enc, &tmWh, pwh, FFTLEN, NTC, (unsigned long long)FFTLEN * sizeof(bf16), 32, NTC);
    encode_2d(enc, &tmWl, pwl, FFTLEN, NTC, (unsigned long long)FFTLEN * sizeof(bf16), 32, NTC);

    cudaFuncSetAttribute(cqt_mma_kernel,
                         cudaFuncAttributeMaxDynamicSharedMemorySize, SMEM_TOTAL);

    cqt_combine_kernel<<<dim3(8, 14), 256>>>(kr, ki, wcos, wsin);
    wpad_kernel<<<192, 256>>>();
    xsplit_kernel<<<(XPAD / 4 + 255) / 256, 256>>>(x);
    cqt_mma_kernel<<<GRID_M, 256, SMEM_TOTAL>>>(tmXh, tmXl, tmWh, tmWl, out);
}

// round 4
// speedup vs baseline: 4.2541x; 1.7282x over previous
#include <cuda_runtime.h>
#include <cuda_bf16.h>
#include <cuda.h>
#include <cstdint>
#include <math.h>

// ---------------- problem constants ----------------
#define NF      16381
#define TS      8388608
#define XPAD    8390144      // 512*16387
#define FFTLEN  2048
#define HOP     512
#define NBINS   84
#define FB      1025
#define NTC     192          // padded N (2*84 -> 192)
#define KC      32
#define NCHUNK  (FFTLEN / KC)   // 64
#define TILE_M  64
#define GRID_M  256
#define NSTAGE  3

// combine GEMM dims
#define KK      2176         // 1088 (wcos, padded) + 1088 (wsin, padded)
#define KHALF   1088
#define NW      (NTC * FFTLEN)   // 393216
#define CCHUNK  17           // K chunks per split (68 total / 4 splits)
#define KSPLIT  4

typedef unsigned long long ull;
typedef __nv_bfloat16 bf16;

// ---------------- scratch ----------------
__device__ __align__(16) bf16  g_xh[XPAD];
__device__ __align__(16) bf16  g_xl[XPAD];
__device__ __align__(16) bf16  g_Wh[NW];
__device__ __align__(16) bf16  g_Wl[NW];
__device__ __align__(16) bf16  g_Ah[2048 * KK];
__device__ __align__(16) bf16  g_Al[2048 * KK];
__device__ __align__(16) bf16  g_Bh[NTC * KK];
__device__ __align__(16) bf16  g_Bl[NTC * KK];
__device__ __align__(16) float g_Wpart[KSPLIT * NW];

// ---------------- base-ISA PTX helpers ----------------
__device__ __forceinline__ uint32_t smem_u32(const void* p) {
    uint32_t a;
    asm("{ .reg .u64 t; cvta.to.shared.u64 t, %1; cvt.u32.u64 %0, t; }" : "=r"(a) : "l"(p));
    return a;
}

#define MBAR_INIT(addr, cnt) \
    asm volatile("mbarrier.init.shared.b64 [%0], %1;" :: "r"((uint32_t)(addr)), "r"((uint32_t)(cnt)) : "memory")
#define MBAR_INVAL(addr) \
    asm volatile("mbarrier.inval.shared.b64 [%0];" :: "r"((uint32_t)(addr)) : "memory")
#define MBAR_ARRIVE(addr) \
    asm volatile("mbarrier.arrive.shared.b64 _, [%0];" :: "r"((uint32_t)(addr)) : "memory")
#define MBAR_EXPECT_TX(addr, bytes) \
    asm volatile("mbarrier.arrive.expect_tx.shared.b64 _, [%0], %1;" \
        :: "r"((uint32_t)(addr)), "r"((uint32_t)(bytes)) : "memory")

#define WAITP(mbar, ph) do { \
    uint32_t _m = (uint32_t)(mbar); uint32_t _p = (uint32_t)(ph); uint32_t _d; \
    asm volatile("{\n\t.reg .pred p;\n\t" \
        "mbarrier.try_wait.parity.acquire.cta.shared::cta.b64 p, [%1], %2;\n\t" \
        "selp.b32 %0, 1, 0, p;\n\t}" : "=r"(_d) : "r"(_m), "r"(_p) : "memory"); \
    if (!_d) { \
        asm volatile("{\n\t.reg .pred P1;\n\t" \
            "WL_%=:\n\t" \
            "mbarrier.try_wait.parity.acquire.cta.shared::cta.b64 P1, [%0], %1, 0x989680;\n\t" \
            "@P1 bra.uni WD_%=;\n\t" \
            "bra.uni WL_%=;\n\t" \
            "WD_%=:\n\t}" :: "r"(_m), "r"(_p) : "memory"); \
    } } while (0)

#define TMA2D(dst, map, x0, y0, mb) \
    asm volatile("cp.async.bulk.tensor.2d.shared::cta.global.tile.mbarrier::complete_tx::bytes " \
        "[%0], [%1, {%2, %3}], [%4];" \
        :: "r"((uint32_t)(dst)), "l"(map), "r"((int)(x0)), "r"((int)(y0)), "r"((uint32_t)(mb)) : "memory")

__device__ __forceinline__ void ldsm4(uint32_t* r, uint32_t addr) {
    asm volatile("ldmatrix.sync.aligned.m8n8.x4.shared.b16 {%0,%1,%2,%3}, [%4];"
        : "=r"(r[0]), "=r"(r[1]), "=r"(r[2]), "=r"(r[3]) : "r"(addr));
}
__device__ __forceinline__ void mma_bf16(float* c, const uint32_t* a, const uint32_t* b) {
    asm volatile("mma.sync.aligned.m16n8k16.row.col.f32.bf16.bf16.f32 "
        "{%0,%1,%2,%3}, {%4,%5,%6,%7}, {%8,%9}, {%0,%1,%2,%3};"
        : "+f"(c[0]), "+f"(c[1]), "+f"(c[2]), "+f"(c[3])
        : "r"(a[0]), "r"(a[1]), "r"(a[2]), "r"(a[3]), "r"(b[0]), "r"(b[1]));
}

// ======================================================================
// Kernel A: transpose wcos/wsin -> A' [2048, 2176] bf16 hi/lo
//   A'[m][kk] = wcos[kk][m] (kk<1025), wsin[kk-1088][m] (1088<=kk<2113), else 0
// grid (64, 68), block 256
// ======================================================================
__global__ __launch_bounds__(256) void atrans_kernel(
    const float* __restrict__ wcos, const float* __restrict__ wsin)
{
    __shared__ float t[32][33];
    const int tx = threadIdx.x & 31;
    const int ty = threadIdx.x >> 5;
    const int m0 = blockIdx.x * 32;
    const int bj = blockIdx.y;
    const float* src;
    int srow0, kk0;
    if (bj < 34) { src = wcos; srow0 = bj * 32;        kk0 = bj * 32; }
    else         { src = wsin; srow0 = (bj - 34) * 32; kk0 = KHALF + (bj - 34) * 32; }

    #pragma unroll
    for (int i = 0; i < 4; i++) {
        const int r  = ty + i * 8;
        const int sr = srow0 + r;
        t[r][tx] = (sr < FB) ? src[sr * FFTLEN + m0 + tx] : 0.f;
    }
    __syncthreads();
    #pragma unroll
    for (int i = 0; i < 4; i++) {
        const int m = m0 + ty + i * 8;
        const float v = t[tx][ty + i * 8];
        bf16 h = __float2bfloat16(v);
        g_Ah[m * KK + kk0 + tx] = h;
        g_Al[m * KK + kk0 + tx] = __float2bfloat16(v - __bfloat162float(h));
    }
}

// ======================================================================
// Kernel B: build B' [192, 2176] from kr/ki (with signs + padding)
// grid (9, 192), block 256
// ======================================================================
__global__ __launch_bounds__(256) void bbuild_kernel(
    const float* __restrict__ kr, const float* __restrict__ ki)
{
    const int kk  = blockIdx.x * 256 + threadIdx.x;
    const int row = blockIdx.y;
    if (kk >= KK) return;
    float v = 0.f;
    if (row < NBINS) {
        if (kk < FB)                          v =  kr[row * FB + kk];
        else if (kk >= KHALF && kk < KHALF + FB) v = -ki[row * FB + kk - KHALF];
    } else if (row < 2 * NBINS) {
        const int j = row - NBINS;
        if (kk < FB)                          v =  ki[j * FB + kk];
        else if (kk >= KHALF && kk < KHALF + FB) v =  kr[j * FB + kk - KHALF];
    }
    bf16 h = __float2bfloat16(v);
    g_Bh[row * KK + kk] = h;
    g_Bl[row * KK + kk] = __float2bfloat16(v - __bfloat162float(h));
}

// ======================================================================
// Kernel C: split x into bf16 hi/lo (zero pad to XPAD)
// ======================================================================
__global__ __launch_bounds__(256) void xsplit_kernel(const float* __restrict__ x) {
    int i = (blockIdx.x * 256 + threadIdx.x) * 4;
    if (i >= XPAD) return;
    float v[4];
    if (i + 4 <= TS) {
        float4 t = *(const float4*)(x + i);
        v[0] = t.x; v[1] = t.y; v[2] = t.z; v[3] = t.w;
    } else {
        #pragma unroll
        for (int j = 0; j < 4; j++) v[j] = (i + j < TS) ? x[i + j] : 0.f;
    }
    union { bf16 b[4]; uint2 u; } H, L;
    #pragma unroll
    for (int j = 0; j < 4; j++) {
        bf16 h = __float2bfloat16(v[j]);
        H.b[j] = h;
        L.b[j] = __float2bfloat16(v[j] - __bfloat162float(h));
    }
    *(uint2*)&g_xh[i] = H.u;
    *(uint2*)&g_xl[i] = L.u;
}

// ======================================================================
// shared pipeline constants (both MMA kernels)
// smem: mbarriers at 0; stages at 1024, each 32KB: Ah 0|Al 4096|Bh 8192|Bl 20480
// ======================================================================
#define STAGE_SZ   32768
#define STAGE0     1024
#define SMEM_TOTAL (STAGE0 + NSTAGE * STAGE_SZ)
#define CHUNK_BYTES 32768

// ======================================================================
// Kernel D: combine GEMM  Wt[m=2048, col=192] = A' @ B'^T, K-split x4
//   partials to g_Wpart[split]
// grid (32, 4), block 256
// ======================================================================
__device__ __forceinline__ void issue_chunk_c(
    uint32_t sb, int s, int m0, int kc,
    const void* tAh, const void* tAl, const void* tBh, const void* tBl)
{
    const uint32_t mb = sb + s * 16;
    const uint32_t st = sb + STAGE0 + s * STAGE_SZ;
    MBAR_EXPECT_TX(mb, CHUNK_BYTES);
    TMA2D(st,         tAh, kc * 32, m0, mb);
    TMA2D(st + 4096,  tAl, kc * 32, m0, mb);
    TMA2D(st + 8192,  tBh, kc * 32, 0, mb);
    TMA2D(st + 20480, tBl, kc * 32, 0, mb);
}

__global__ __launch_bounds__(256, 2) void comb_mma_kernel(
    const __grid_constant__ CUtensorMap tmAh,
    const __grid_constant__ CUtensorMap tmAl,
    const __grid_constant__ CUtensorMap tmBh,
    const __grid_constant__ CUtensorMap tmBl)
{
    extern __shared__ __align__(1024) char smem[];
    const uint32_t sb = smem_u32(smem);
    const int tid  = threadIdx.x;
    const int wid  = tid >> 5;
    const int lane = tid & 31;
    const int wm   = wid & 1;
    const int wn   = wid >> 1;
    const int m0   = blockIdx.x * TILE_M;
    const int ksb  = blockIdx.y * CCHUNK;

    const int arow  = wm * 32 + (lane & 15);
    const int akb   = (lane >> 4) * 16;
    const int aswz  = ((arow >> 1) & 3) << 4;
    const int abase = arow * 64;
    const int brown = (lane & 7) + ((lane & 16) ? 8 : 0);
    const int bkb   = (lane & 8) ? 16 : 0;
    const int bswz  = ((brown >> 1) & 3) << 4;
    const int bbase = (wn * 48 + brown) * 64;

    if (tid == 0) {
        #pragma unroll
        for (int s = 0; s < NSTAGE; s++) {
            MBAR_INIT(sb + s * 16, 1);
            MBAR_INIT(sb + s * 16 + 8, 256);
        }
    }
    __syncthreads();
    if (tid == 0) {
        #pragma unroll
        for (int s = 0; s < NSTAGE; s++)
            issue_chunk_c(sb, s, m0, ksb + s, &tmAh, &tmAl, &tmBh, &tmBl);
    }

    float acc[2][6][4];
    #pragma unroll
    for (int t = 0; t < 2; t++)
        #pragma unroll
        for (int j = 0; j < 6; j++)
            #pragma unroll
            for (int q = 0; q < 4; q++) acc[t][j][q] = 0.f;

    int fph[NSTAGE] = {0, 0, 0};
    int eph[NSTAGE] = {0, 0, 0};

    for (int c = 0; c < CCHUNK; ++c) {
        const int s = c % NSTAGE;
        WAITP(sb + s * 16, fph[s]); fph[s] ^= 1;
        const uint32_t st = sb + STAGE0 + s * STAGE_SZ;

        #pragma unroll
        for (int ks = 0; ks < 2; ++ks) {
            uint32_t ah[2][4], alr[2][4], bh[6][2], blr[6][2];
            #pragma unroll
            for (int t = 0; t < 2; ++t) {
                const uint32_t ao = abase + t * 1024 + ((ks * 32 + akb) ^ aswz);
                ldsm4(ah[t],  st + ao);
                ldsm4(alr[t], st + 4096 + ao);
            }
            #pragma unroll
            for (int j2 = 0; j2 < 3; ++j2) {
                const uint32_t bo = bbase + j2 * 1024 + ((ks * 32 + bkb) ^ bswz);
                uint32_t r4[4];
                ldsm4(r4, st + 8192 + bo);
                bh[2*j2][0] = r4[0]; bh[2*j2][1] = r4[1];
                bh[2*j2+1][0] = r4[2]; bh[2*j2+1][1] = r4[3];
                ldsm4(r4, st + 20480 + bo);
                blr[2*j2][0] = r4[0]; blr[2*j2][1] = r4[1];
                blr[2*j2+1][0] = r4[2]; blr[2*j2+1][1] = r4[3];
            }
            #pragma unroll
            for (int t = 0; t < 2; ++t)
                #pragma unroll
                for (int j = 0; j < 6; ++j) {
                    mma_bf16(acc[t][j], ah[t],  bh[j]);
                    mma_bf16(acc[t][j], ah[t],  blr[j]);
                    mma_bf16(acc[t][j], alr[t], bh[j]);
                }
        }

        MBAR_ARRIVE(sb + s * 16 + 8);
        if (tid == 0 && c + NSTAGE < CCHUNK) {
            WAITP(sb + s * 16 + 8, eph[s]); eph[s] ^= 1;
            issue_chunk_c(sb, s, m0, ksb + c + NSTAGE, &tmAh, &tmAl, &tmBh, &tmBl);
        }
    }

    __syncthreads();
    float* Cs = (float*)(smem + STAGE0);   // [192][68]
    const int g  = lane >> 2;
    const int tc = lane & 3;
    #pragma unroll
    for (int t = 0; t < 2; ++t) {
        const int r0 = wm * 32 + t * 16 + g;
        #pragma unroll
        for (int j = 0; j < 6; ++j) {
            const int col = wn * 48 + j * 8 + tc * 2;
            Cs[col * 68 + r0]           = acc[t][j][0];
            Cs[(col + 1) * 68 + r0]     = acc[t][j][1];
            Cs[col * 68 + r0 + 8]       = acc[t][j][2];
            Cs[(col + 1) * 68 + r0 + 8] = acc[t][j][3];
        }
    }
    __syncthreads();
    float* dst = g_Wpart + blockIdx.y * NW;
    #pragma unroll
    for (int i = tid; i < NTC * TILE_M; i += 256) {
        const int bin = i >> 6;
        const int r   = i & 63;
        dst[bin * FFTLEN + m0 + r] = Cs[bin * 68 + r];
    }

    __syncthreads();
    if (tid == 0) {
        #pragma unroll
        for (int s = 0; s < NSTAGE; s++) { MBAR_INVAL(sb + s * 16); MBAR_INVAL(sb + s * 16 + 8); }
    }
}

// ======================================================================
// Kernel E: reduce 4 partials -> W bf16 hi/lo
// ======================================================================
__global__ __launch_bounds__(256) void wconvert_kernel() {
    const int i = (blockIdx.x * 256 + threadIdx.x) * 4;
    if (i >= NW) return;
    float4 a = *(const float4*)&g_Wpart[i];
    float4 b = *(const float4*)&g_Wpart[NW + i];
    float4 c = *(const float4*)&g_Wpart[2 * NW + i];
    float4 d = *(const float4*)&g_Wpart[3 * NW + i];
    float v[4] = {a.x + b.x + c.x + d.x, a.y + b.y + c.y + d.y,
                  a.z + b.z + c.z + d.z, a.w + b.w + c.w + d.w};
    union { bf16 bb[4]; uint2 u; } H, L;
    #pragma unroll
    for (int j = 0; j < 4; j++) {
        bf16 h = __float2bfloat16(v[j]);
        H.bb[j] = h;
        L.bb[j] = __float2bfloat16(v[j] - __bfloat162float(h));
    }
    *(uint2*)&g_Wh[i] = H.u;
    *(uint2*)&g_Wl[i] = L.u;
}

// ======================================================================
// Kernel F: main HMMA GEMM + magnitude epilogue (unchanged from R3)
// ======================================================================
__device__ __forceinline__ void issue_chunk(
    uint32_t sb, int s, int f0, int c,
    const void* tXh, const void* tXl, const void* tWh, const void* tWl)
{
    const uint32_t mb = sb + s * 16;
    const uint32_t st = sb + STAGE0 + s * STAGE_SZ;
    const int kx = (c & 15) * 32;
    const int ky = f0 + (c >> 4);
    MBAR_EXPECT_TX(mb, CHUNK_BYTES);
    TMA2D(st,         tXh, kx, ky, mb);
    TMA2D(st + 4096,  tXl, kx, ky, mb);
    TMA2D(st + 8192,  tWh, c * 32, 0, mb);
    TMA2D(st + 20480, tWl, c * 32, 0, mb);
}

__global__ __launch_bounds__(256, 2) void cqt_mma_kernel(
    const __grid_constant__ CUtensorMap tmXh,
    const __grid_constant__ CUtensorMap tmXl,
    const __grid_constant__ CUtensorMap tmWh,
    const __grid_constant__ CUtensorMap tmWl,
    float* __restrict__ out)
{
    extern __shared__ __align__(1024) char smem[];
    const uint32_t sb = smem_u32(smem);
    const int tid  = threadIdx.x;
    const int wid  = tid >> 5;
    const int lane = tid & 31;
    const int wm   = wid & 1;
    const int wn   = wid >> 1;
    const int f0   = blockIdx.x * TILE_M;

    const int arow  = wm * 32 + (lane & 15);
    const int akb   = (lane >> 4) * 16;
    const int aswz  = ((arow >> 1) & 3) << 4;
    const int abase = arow * 64;
    const int brown = (lane & 7) + ((lane & 16) ? 8 : 0);
    const int bkb   = (lane & 8) ? 16 : 0;
    const int bswz  = ((brown >> 1) & 3) << 4;
    const int bbase = (wn * 48 + brown) * 64;

    if (tid == 0) {
        #pragma unroll
        for (int s = 0; s < NSTAGE; s++) {
            MBAR_INIT(sb + s * 16, 1);
            MBAR_INIT(sb + s * 16 + 8, 256);
        }
    }
    __syncthreads();
    if (tid == 0) {
        #pragma unroll
        for (int s = 0; s < NSTAGE; s++)
            issue_chunk(sb, s, f0, s, &tmXh, &tmXl, &tmWh, &tmWl);
    }

    float acc[2][6][4];
    #pragma unroll
    for (int t = 0; t < 2; t++)
        #pragma unroll
        for (int j = 0; j < 6; j++)
            #pragma unroll
            for (int q = 0; q < 4; q++) acc[t][j][q] = 0.f;

    int fph[NSTAGE] = {0, 0, 0};
    int eph[NSTAGE] = {0, 0, 0};

    for (int c = 0; c < NCHUNK; ++c) {
        const int s = c % NSTAGE;
        WAITP(sb + s * 16, fph[s]); fph[s] ^= 1;
        const uint32_t st = sb + STAGE0 + s * STAGE_SZ;

        #pragma unroll
        for (int ks = 0; ks < 2; ++ks) {
            uint32_t ah[2][4], alr[2][4], bh[6][2], blr[6][2];
            #pragma unroll
            for (int t = 0; t < 2; ++t) {
                const uint32_t ao = abase + t * 1024 + ((ks * 32 + akb) ^ aswz);
                ldsm4(ah[t],  st + ao);
                ldsm4(alr[t], st + 4096 + ao);
            }
            #pragma unroll
            for (int j2 = 0; j2 < 3; ++j2) {
                const uint32_t bo = bbase + j2 * 1024 + ((ks * 32 + bkb) ^ bswz);
                uint32_t r4[4];
                ldsm4(r4, st + 8192 + bo);
                bh[2*j2][0] = r4[0]; bh[2*j2][1] = r4[1];
                bh[2*j2+1][0] = r4[2]; bh[2*j2+1][1] = r4[3];
                ldsm4(r4, st + 20480 + bo);
                blr[2*j2][0] = r4[0]; blr[2*j2][1] = r4[1];
                blr[2*j2+1][0] = r4[2]; blr[2*j2+1][1] = r4[3];
            }
            #pragma unroll
            for (int t = 0; t < 2; ++t)
                #pragma unroll
                for (int j = 0; j < 6; ++j) {
                    mma_bf16(acc[t][j], ah[t],  bh[j]);
                    mma_bf16(acc[t][j], ah[t],  blr[j]);
                    mma_bf16(acc[t][j], alr[t], bh[j]);
                }
        }

        MBAR_ARRIVE(sb + s * 16 + 8);
        if (tid == 0 && c + NSTAGE < NCHUNK) {
            WAITP(sb + s * 16 + 8, eph[s]); eph[s] ^= 1;
            issue_chunk(sb, s, f0, c + NSTAGE, &tmXh, &tmXl, &tmWh, &tmWl);
        }
    }

    __syncthreads();
    float* Cs = (float*)(smem + STAGE0);   // [192][68]
    const int g  = lane >> 2;
    const int tc = lane & 3;
    #pragma unroll
    for (int t = 0; t < 2; ++t) {
        const int r0 = wm * 32 + t * 16 + g;
        #pragma unroll
        for (int j = 0; j < 6; ++j) {
            const int col = wn * 48 + j * 8 + tc * 2;
            Cs[col * 68 + r0]           = acc[t][j][0];
            Cs[(col + 1) * 68 + r0]     = acc[t][j][1];
            Cs[col * 68 + r0 + 8]       = acc[t][j][2];
            Cs[(col + 1) * 68 + r0 + 8] = acc[t][j][3];
        }
    }
    __syncthreads();
    #pragma unroll
    for (int i = tid; i < NBINS * TILE_M; i += 256) {
        const int bin = i >> 6;
        const int r   = i & 63;
        const int f   = f0 + r;
        if (f < NF) {
            const float re = Cs[bin * 68 + r];
            const float im = Cs[(bin + NBINS) * 68 + r];
            out[bin * NF + f] = sqrtf(re * re + im * im);
        }
    }

    __syncthreads();
    if (tid == 0) {
        #pragma unroll
        for (int s = 0; s < NSTAGE; s++) { MBAR_INVAL(sb + s * 16); MBAR_INVAL(sb + s * 16 + 8); }
    }
}

// ======================================================================
// host side
// ======================================================================
typedef CUresult (CUDAAPI *EncodeFn)(
    CUtensorMap*, CUtensorMapDataType, cuuint32_t, void*,
    const cuuint64_t*, const cuuint64_t*, const cuuint32_t*, const cuuint32_t*,
    CUtensorMapInterleave, CUtensorMapSwizzle, CUtensorMapL2promotion,
    CUtensorMapFloatOOBfill);

static void encode_2d(EncodeFn enc, CUtensorMap* tm, void* ptr,
                      unsigned long long d0, unsigned long long d1,
                      unsigned long long strideB,
                      unsigned box0, unsigned box1) {
    cuuint64_t dims[2] = {d0, d1};
    cuuint64_t str[1]  = {strideB};
    cuuint32_t box[2]  = {box0, box1};
    cuuint32_t es[2]   = {1, 1};
    enc(tm, CU_TENSOR_MAP_DATA_TYPE_BFLOAT16, 2, ptr, dims, str, box, es,
        CU_TENSOR_MAP_INTERLEAVE_NONE, CU_TENSOR_MAP_SWIZZLE_64B,
        CU_TENSOR_MAP_L2_PROMOTION_L2_128B, CU_TENSOR_MAP_FLOAT_OOB_FILL_NONE);
}

extern "C" void kernel_launch(void* const* d_in, const int* in_sizes, int n_in,
                              void* d_out, int out_size) {
    const float* x    = (const float*)d_in[0];
    const float* wcos = (const float*)d_in[1];
    const float* wsin = (const float*)d_in[2];
    const float* kr   = (const float*)d_in[3];
    const float* ki   = (const float*)d_in[4];
    float* out = (float*)d_out;

    void* fn = nullptr;
    cudaDriverEntryPointQueryResult st;
#if CUDART_VERSION >= 12050
    cudaGetDriverEntryPointByVersion("cuTensorMapEncodeTiled", &fn, 12000,
                                     cudaEnableDefault, &st);
#else
    cudaGetDriverEntryPoint("cuTensorMapEncodeTiled", &fn, cudaEnableDefault, &st);
#endif
    EncodeFn enc = (EncodeFn)fn;

    void *pxh, *pxl, *pwh, *pwl, *pah, *pal, *pbh, *pbl;
    cudaGetSymbolAddress(&pxh, g_xh);
    cudaGetSymbolAddress(&pxl, g_xl);
    cudaGetSymbolAddress(&pwh, g_Wh);
    cudaGetSymbolAddress(&pwl, g_Wl);
    cudaGetSymbolAddress(&pah, g_Ah);
    cudaGetSymbolAddress(&pal, g_Al);
    cudaGetSymbolAddress(&pbh, g_Bh);
    cudaGetSymbolAddress(&pbl, g_Bl);

    CUtensorMap tmXh, tmXl, tmWh, tmWl, tmAh, tmAl, tmBh, tmBl;
    encode_2d(enc, &tmXh, pxh, 512, 16387, 512ull * sizeof(bf16), 32, TILE_M);
    encode_2d(enc, &tmXl, pxl, 512, 16387, 512ull * sizeof(bf16), 32, TILE_M);
    encode_2d(enc, &tmWh, pwh, FFTLEN, NTC, (unsigned long long)FFTLEN * sizeof(bf16), 32, NTC);
    encode_2d(enc, &tmWl, pwl, FFTLEN, NTC, (unsigned long long)FFTLEN * sizeof(bf16), 32, NTC);
    encode_2d(enc, &tmAh, pah, KK, 2048, (unsigned long long)KK * sizeof(bf16), 32, TILE_M);
    encode_2d(enc, &tmAl, pal, KK, 2048, (unsigned long long)KK * sizeof(bf16), 32, TILE_M);
    encode_2d(enc, &tmBh, pbh, KK, NTC, (unsigned long long)KK * sizeof(bf16), 32, NTC);
    encode_2d(enc, &tmBl, pbl, KK, NTC, (unsigned long long)KK * sizeof(bf16), 32, NTC);

    cudaFuncSetAttribute(cqt_mma_kernel,
                         cudaFuncAttributeMaxDynamicSharedMemorySize, SMEM_TOTAL);
    cudaFuncSetAttribute(comb_mma_kernel,
                         cudaFuncAttributeMaxDynamicSharedMemorySize, SMEM_TOTAL);

    atrans_kernel<<<dim3(64, 68), 256>>>(wcos, wsin);
    bbuild_kernel<<<dim3(9, 192), 256>>>(kr, ki);
    xsplit_kernel<<<(XPAD / 4 + 255) / 256, 256>>>(x);
    comb_mma_kernel<<<dim3(32, KSPLIT), 256, SMEM_TOTAL>>>(tmAh, tmAl, tmBh, tmBl);
    wconvert_kernel<<<NW / 1024, 256>>>();
    cqt_mma_kernel<<<GRID_M, 256, SMEM_TOTAL>>>(tmXh, tmXl, tmWh, tmWl, out);
}

// round 6
// speedup vs baseline: 5.0540x; 1.1880x over previous
#include <cuda_runtime.h>
#include <cuda_bf16.h>
#include <cuda_fp16.h>
#include <cuda.h>
#include <cstdint>
#include <math.h>

// ---------------- problem constants ----------------
#define NF      16381
#define TS      8388608
#define XPAD    8390144      // 512*16387
#define FFTLEN  2048
#define HOP     512
#define NBINS   84
#define FB      1025
#define NTC     192          // padded N (2*84 -> 192)
#define KC      32
#define NCHUNK  (FFTLEN / KC)   // 64
#define TILE_M  64
#define GRID_M  256

// combine GEMM dims
#define KK      2176
#define KHALF   1088
#define NW      (NTC * FFTLEN)   // 393216
#define KSPLIT  8

typedef unsigned long long ull;
typedef __nv_bfloat16 bf16;
typedef __half fp16;

// ---------------- scratch ----------------
__device__ __align__(16) fp16  g_xh[XPAD];
__device__ __align__(16) fp16  g_xl[XPAD];
__device__ __align__(16) fp16  g_Wf[NW];          // scaled fp16 W
__device__ __align__(16) float g_sInv[NTC];       // per-row 1/scale
__device__ __align__(16) bf16  g_Ah[2048 * KK];
__device__ __align__(16) bf16  g_Al[2048 * KK];
__device__ __align__(16) bf16  g_Bh[NTC * KK];
__device__ __align__(16) bf16  g_Bl[NTC * KK];
__device__ __align__(16) float g_Wpart[KSPLIT * NW];

// ---------------- base-ISA PTX helpers ----------------
__device__ __forceinline__ uint32_t smem_u32(const void* p) {
    uint32_t a;
    asm("{ .reg .u64 t; cvta.to.shared.u64 t, %1; cvt.u32.u64 %0, t; }" : "=r"(a) : "l"(p));
    return a;
}

#define MBAR_INIT(addr, cnt) \
    asm volatile("mbarrier.init.shared.b64 [%0], %1;" :: "r"((uint32_t)(addr)), "r"((uint32_t)(cnt)) : "memory")
#define MBAR_INVAL(addr) \
    asm volatile("mbarrier.inval.shared.b64 [%0];" :: "r"((uint32_t)(addr)) : "memory")
#define MBAR_ARRIVE(addr) \
    asm volatile("mbarrier.arrive.shared.b64 _, [%0];" :: "r"((uint32_t)(addr)) : "memory")
#define MBAR_EXPECT_TX(addr, bytes) \
    asm volatile("mbarrier.arrive.expect_tx.shared.b64 _, [%0], %1;" \
        :: "r"((uint32_t)(addr)), "r"((uint32_t)(bytes)) : "memory")

#define WAITP(mbar, ph) do { \
    uint32_t _m = (uint32_t)(mbar); uint32_t _p = (uint32_t)(ph); uint32_t _d; \
    asm volatile("{\n\t.reg .pred p;\n\t" \
        "mbarrier.try_wait.parity.acquire.cta.shared::cta.b64 p, [%1], %2;\n\t" \
        "selp.b32 %0, 1, 0, p;\n\t}" : "=r"(_d) : "r"(_m), "r"(_p) : "memory"); \
    if (!_d) { \
        asm volatile("{\n\t.reg .pred P1;\n\t" \
            "WL_%=:\n\t" \
            "mbarrier.try_wait.parity.acquire.cta.shared::cta.b64 P1, [%0], %1, 0x989680;\n\t" \
            "@P1 bra.uni WD_%=;\n\t" \
            "bra.uni WL_%=;\n\t" \
            "WD_%=:\n\t}" :: "r"(_m), "r"(_p) : "memory"); \
    } } while (0)

#define TMA2D(dst, map, x0, y0, mb) \
    asm volatile("cp.async.bulk.tensor.2d.shared::cta.global.tile.mbarrier::complete_tx::bytes " \
        "[%0], [%1, {%2, %3}], [%4];" \
        :: "r"((uint32_t)(dst)), "l"(map), "r"((int)(x0)), "r"((int)(y0)), "r"((uint32_t)(mb)) : "memory")

__device__ __forceinline__ void ldsm4(uint32_t* r, uint32_t addr) {
    asm volatile("ldmatrix.sync.aligned.m8n8.x4.shared.b16 {%0,%1,%2,%3}, [%4];"
        : "=r"(r[0]), "=r"(r[1]), "=r"(r[2]), "=r"(r[3]) : "r"(addr));
}
__device__ __forceinline__ void mma_bf16(float* c, const uint32_t* a, const uint32_t* b) {
    asm volatile("mma.sync.aligned.m16n8k16.row.col.f32.bf16.bf16.f32 "
        "{%0,%1,%2,%3}, {%4,%5,%6,%7}, {%8,%9}, {%0,%1,%2,%3};"
        : "+f"(c[0]), "+f"(c[1]), "+f"(c[2]), "+f"(c[3])
        : "r"(a[0]), "r"(a[1]), "r"(a[2]), "r"(a[3]), "r"(b[0]), "r"(b[1]));
}
__device__ __forceinline__ void mma_fp16(float* c, const uint32_t* a, const uint32_t* b) {
    asm volatile("mma.sync.aligned.m16n8k16.row.col.f32.f16.f16.f32 "
        "{%0,%1,%2,%3}, {%4,%5,%6,%7}, {%8,%9}, {%0,%1,%2,%3};"
        : "+f"(c[0]), "+f"(c[1]), "+f"(c[2]), "+f"(c[3])
        : "r"(a[0]), "r"(a[1]), "r"(a[2]), "r"(a[3]), "r"(b[0]), "r"(b[1]));
}

// ======================================================================
// Kernel 1 (merged prep): atrans | bbuild | xsplit in one launch
// ======================================================================
#define ATR_BLKS  4352          // 64 * 68
#define BB_BLKS   1728          // 9 * 192
#define XS_BLKS   8194
#define PREP_BLKS (ATR_BLKS + BB_BLKS + XS_BLKS)

__global__ __launch_bounds__(256) void prep_kernel(
    const float* __restrict__ x,
    const float* __restrict__ wcos, const float* __restrict__ wsin,
    const float* __restrict__ kr,   const float* __restrict__ ki)
{
    __shared__ float t[32][33];
    const int blk = blockIdx.x;
    const int tid = threadIdx.x;

    if (blk < ATR_BLKS) {
        // ---- transpose wcos/wsin -> A' bf16 hi/lo ----
        const int tx = tid & 31, ty = tid >> 5;
        const int m0 = (blk & 63) * 32;
        const int bj = blk >> 6;
        const float* src;
        int srow0, kk0;
        if (bj < 34) { src = wcos; srow0 = bj * 32;        kk0 = bj * 32; }
        else         { src = wsin; srow0 = (bj - 34) * 32; kk0 = KHALF + (bj - 34) * 32; }
        #pragma unroll
        for (int i = 0; i < 4; i++) {
            const int r  = ty + i * 8;
            const int sr = srow0 + r;
            t[r][tx] = (sr < FB) ? src[sr * FFTLEN + m0 + tx] : 0.f;
        }
        __syncthreads();
        #pragma unroll
        for (int i = 0; i < 4; i++) {
            const int m = m0 + ty + i * 8;
            const float v = t[tx][ty + i * 8];
            bf16 h = __float2bfloat16(v);
            g_Ah[m * KK + kk0 + tx] = h;
            g_Al[m * KK + kk0 + tx] = __float2bfloat16(v - __bfloat162float(h));
        }
    } else if (blk < ATR_BLKS + BB_BLKS) {
        // ---- build B' [192, 2176] bf16 hi/lo ----
        const int b2  = blk - ATR_BLKS;
        const int kk  = (b2 % 9) * 256 + tid;
        const int row = b2 / 9;
        if (kk >= KK) return;
        float v = 0.f;
        if (row < NBINS) {
            if (kk < FB)                             v =  kr[row * FB + kk];
            else if (kk >= KHALF && kk < KHALF + FB) v = -ki[row * FB + kk - KHALF];
        } else if (row < 2 * NBINS) {
            const int j = row - NBINS;
            if (kk < FB)                             v =  ki[j * FB + kk];
            else if (kk >= KHALF && kk < KHALF + FB) v =  kr[j * FB + kk - KHALF];
        }
        bf16 h = __float2bfloat16(v);
        g_Bh[row * KK + kk] = h;
        g_Bl[row * KK + kk] = __float2bfloat16(v - __bfloat162float(h));
    } else {
        // ---- split x -> fp16 hi/lo, zero pad to XPAD ----
        const int i = ((blk - ATR_BLKS - BB_BLKS) * 256 + tid) * 4;
        if (i >= XPAD) return;
        float v[4];
        if (i + 4 <= TS) {
            float4 q = *(const float4*)(x + i);
            v[0] = q.x; v[1] = q.y; v[2] = q.z; v[3] = q.w;
        } else {
            #pragma unroll
            for (int j = 0; j < 4; j++) v[j] = (i + j < TS) ? x[i + j] : 0.f;
        }
        union { fp16 h[4]; uint2 u; } H, L;
        #pragma unroll
        for (int j = 0; j < 4; j++) {
            fp16 h = __float2half(v[j]);
            H.h[j] = h;
            L.h[j] = __float2half(v[j] - __half2float(h));
        }
        *(uint2*)&g_xh[i] = H.u;
        *(uint2*)&g_xl[i] = L.u;
    }
}

// ======================================================================
// Kernel 2: combine GEMM Wt = A' @ B'^T  (bf16 3-product), K-split x8
// ======================================================================
#define CSTAGE     3
#define CSTG_SZ    32768
#define CSTAGE0    1024
#define CSMEM      (CSTAGE0 + CSTAGE * CSTG_SZ)
#define CCHB       32768

__device__ __forceinline__ void issue_chunk_c(
    uint32_t sb, int s, int m0, int kc,
    const void* tAh, const void* tAl, const void* tBh, const void* tBl)
{
    const uint32_t mb = sb + s * 16;
    const uint32_t st = sb + CSTAGE0 + s * CSTG_SZ;
    MBAR_EXPECT_TX(mb, CCHB);
    TMA2D(st,         tAh, kc * 32, m0, mb);
    TMA2D(st + 4096,  tAl, kc * 32, m0, mb);
    TMA2D(st + 8192,  tBh, kc * 32, 0, mb);
    TMA2D(st + 20480, tBl, kc * 32, 0, mb);
}

__global__ __launch_bounds__(256, 2) void comb_mma_kernel(
    const __grid_constant__ CUtensorMap tmAh,
    const __grid_constant__ CUtensorMap tmAl,
    const __grid_constant__ CUtensorMap tmBh,
    const __grid_constant__ CUtensorMap tmBl)
{
    extern __shared__ __align__(1024) char smem[];
    const uint32_t sb = smem_u32(smem);
    const int tid  = threadIdx.x;
    const int wid  = tid >> 5;
    const int lane = tid & 31;
    const int wm   = wid & 1;
    const int wn   = wid >> 1;
    const int m0   = blockIdx.x * TILE_M;
    const int sp   = blockIdx.y;
    const int nch  = (sp < 4) ? 9 : 8;
    const int ksb  = (sp < 4) ? sp * 9 : 36 + (sp - 4) * 8;

    const int arow  = wm * 32 + (lane & 15);
    const int akb   = (lane >> 4) * 16;
    const int aswz  = ((arow >> 1) & 3) << 4;
    const int abase = arow * 64;
    const int brown = (lane & 7) + ((lane & 16) ? 8 : 0);
    const int bkb   = (lane & 8) ? 16 : 0;
    const int bswz  = ((brown >> 1) & 3) << 4;
    const int bbase = (wn * 48 + brown) * 64;

    if (tid == 0) {
        #pragma unroll
        for (int s = 0; s < CSTAGE; s++) {
            MBAR_INIT(sb + s * 16, 1);
            MBAR_INIT(sb + s * 16 + 8, 256);
        }
    }
    __syncthreads();
    if (tid == 0) {
        #pragma unroll
        for (int s = 0; s < CSTAGE; s++)
            issue_chunk_c(sb, s, m0, ksb + s, &tmAh, &tmAl, &tmBh, &tmBl);
    }

    float acc[2][6][4];
    #pragma unroll
    for (int t = 0; t < 2; t++)
        #pragma unroll
        for (int j = 0; j < 6; j++)
            #pragma unroll
            for (int q = 0; q < 4; q++) acc[t][j][q] = 0.f;

    int fph[CSTAGE] = {0, 0, 0};
    int eph[CSTAGE] = {0, 0, 0};

    for (int c = 0; c < nch; ++c) {
        const int s = c % CSTAGE;
        WAITP(sb + s * 16, fph[s]); fph[s] ^= 1;
        const uint32_t st = sb + CSTAGE0 + s * CSTG_SZ;

        #pragma unroll
        for (int ks = 0; ks < 2; ++ks) {
            uint32_t ah[2][4], alr[2][4], bh[6][2], blr[6][2];
            #pragma unroll
            for (int t = 0; t < 2; ++t) {
                const uint32_t ao = abase + t * 1024 + ((ks * 32 + akb) ^ aswz);
                ldsm4(ah[t],  st + ao);
                ldsm4(alr[t], st + 4096 + ao);
            }
            #pragma unroll
            for (int j2 = 0; j2 < 3; ++j2) {
                const uint32_t bo = bbase + j2 * 1024 + ((ks * 32 + bkb) ^ bswz);
                uint32_t r4[4];
                ldsm4(r4, st + 8192 + bo);
                bh[2*j2][0] = r4[0]; bh[2*j2][1] = r4[1];
                bh[2*j2+1][0] = r4[2]; bh[2*j2+1][1] = r4[3];
                ldsm4(r4, st + 20480 + bo);
                blr[2*j2][0] = r4[0]; blr[2*j2][1] = r4[1];
                blr[2*j2+1][0] = r4[2]; blr[2*j2+1][1] = r4[3];
            }
            #pragma unroll
            for (int t = 0; t < 2; ++t)
                #pragma unroll
                for (int j = 0; j < 6; ++j) {
                    mma_bf16(acc[t][j], ah[t],  bh[j]);
                    mma_bf16(acc[t][j], ah[t],  blr[j]);
                    mma_bf16(acc[t][j], alr[t], bh[j]);
                }
        }

        MBAR_ARRIVE(sb + s * 16 + 8);
        if (tid == 0 && c + CSTAGE < nch) {
            WAITP(sb + s * 16 + 8, eph[s]); eph[s] ^= 1;
            issue_chunk_c(sb, s, m0, ksb + c + CSTAGE, &tmAh, &tmAl, &tmBh, &tmBl);
        }
    }

    __syncthreads();
    float* Cs = (float*)(smem + CSTAGE0);   // [192][68]
    const int g  = lane >> 2;
    const int tc = lane & 3;
    #pragma unroll
    for (int t = 0; t < 2; ++t) {
        const int r0 = wm * 32 + t * 16 + g;
        #pragma unroll
        for (int j = 0; j < 6; ++j) {
            const int col = wn * 48 + j * 8 + tc * 2;
            Cs[col * 68 + r0]           = acc[t][j][0];
            Cs[(col + 1) * 68 + r0]     = acc[t][j][1];
            Cs[col * 68 + r0 + 8]       = acc[t][j][2];
            Cs[(col + 1) * 68 + r0 + 8] = acc[t][j][3];
        }
    }
    __syncthreads();
    float* dst = g_Wpart + sp * NW;
    #pragma unroll
    for (int i = tid; i < NTC * TILE_M; i += 256) {
        const int bin = i >> 6;
        const int r   = i & 63;
        dst[bin * FFTLEN + m0 + r] = Cs[bin * 68 + r];
    }

    __syncthreads();
    if (tid == 0) {
        #pragma unroll
        for (int s = 0; s < CSTAGE; s++) { MBAR_INVAL(sb + s * 16); MBAR_INVAL(sb + s * 16 + 8); }
    }
}

// ======================================================================
// Kernel 3: reduce 8 partials -> row max -> scale -> fp16 W  (192 blocks)
// ======================================================================
__global__ __launch_bounds__(256) void wconvert_kernel() {
    __shared__ float red[8];
    const int row  = blockIdx.x;
    const int base = row * FFTLEN;
    const int tid  = threadIdx.x;

    float v[8];
    float mx = 0.f;
    #pragma unroll
    for (int j = 0; j < 8; j++) {
        const int col = tid + j * 256;
        float s = 0.f;
        #pragma unroll
        for (int p = 0; p < KSPLIT; p++) s += g_Wpart[p * NW + base + col];
        v[j] = s;
        mx = fmaxf(mx, fabsf(s));
    }
    #pragma unroll
    for (int o = 16; o; o >>= 1) mx = fmaxf(mx, __shfl_xor_sync(0xFFFFFFFFu, mx, o));
    if ((tid & 31) == 0) red[tid >> 5] = mx;
    __syncthreads();
    float m = red[0];
    #pragma unroll
    for (int w = 1; w < 8; w++) m = fmaxf(m, red[w]);

    float s = 1.f, si = 1.f;
    if (m > 1e-30f) {
        const int e = ilogbf(m);
        s  = exp2f((float)(14 - e));
        si = exp2f((float)(e - 14));
    }
    if (tid == 0) g_sInv[row] = si;
    #pragma unroll
    for (int j = 0; j < 8; j++)
        g_Wf[base + tid + j * 256] = __float2half(v[j] * s);
}

// ======================================================================
// Kernel 4: main fp16 GEMM (2 products) + magnitude epilogue
//   stage: Ah 4KB | Al 4KB | B 12KB = 20KB, 5 stages, 2 CTAs/SM
// ======================================================================
#define MSTAGE   5
#define MSTG_SZ  20480
#define MSTAGE0  1024
#define MSMEM    (MSTAGE0 + MSTAGE * MSTG_SZ)   // 103424
#define MCHB     20480

__device__ __forceinline__ void issue_chunk_m(
    uint32_t sb, int s, int f0, int c,
    const void* tXh, const void* tXl, const void* tW)
{
    const uint32_t mb = sb + s * 16;
    const uint32_t st = sb + MSTAGE0 + s * MSTG_SZ;
    const int kx = (c & 15) * 32;
    const int ky = f0 + (c >> 4);
    MBAR_EXPECT_TX(mb, MCHB);
    TMA2D(st,        tXh, kx, ky, mb);
    TMA2D(st + 4096, tXl, kx, ky, mb);
    TMA2D(st + 8192, tW,  c * 32, 0, mb);
}

__global__ __launch_bounds__(256, 2) void cqt_mma_kernel(
    const __grid_constant__ CUtensorMap tmXh,
    const __grid_constant__ CUtensorMap tmXl,
    const __grid_constant__ CUtensorMap tmW,
    float* __restrict__ out)
{
    extern __shared__ __align__(1024) char smem[];
    const uint32_t sb = smem_u32(smem);
    const int tid  = threadIdx.x;
    const int wid  = tid >> 5;
    const int lane = tid & 31;
    const int wm   = wid & 1;
    const int wn   = wid >> 1;
    const int f0   = blockIdx.x * TILE_M;

    const int arow  = wm * 32 + (lane & 15);
    const int akb   = (lane >> 4) * 16;
    const int aswz  = ((arow >> 1) & 3) << 4;
    const int abase = arow * 64;
    const int brown = (lane & 7) + ((lane & 16) ? 8 : 0);
    const int bkb   = (lane & 8) ? 16 : 0;
    const int bswz  = ((brown >> 1) & 3) << 4;
    const int bbase = (wn * 48 + brown) * 64;

    if (tid == 0) {
        #pragma unroll
        for (int s = 0; s < MSTAGE; s++) {
            MBAR_INIT(sb + s * 16, 1);
            MBAR_INIT(sb + s * 16 + 8, 256);
        }
    }
    __syncthreads();
    if (tid == 0) {
        #pragma unroll
        for (int s = 0; s < MSTAGE; s++)
            issue_chunk_m(sb, s, f0, s, &tmXh, &tmXl, &tmW);
    }

    float acc[2][6][4];
    #pragma unroll
    for (int t = 0; t < 2; t++)
        #pragma unroll
        for (int j = 0; j < 6; j++)
            #pragma unroll
            for (int q = 0; q < 4; q++) acc[t][j][q] = 0.f;

    int fph[MSTAGE] = {0, 0, 0, 0, 0};
    int eph[MSTAGE] = {0, 0, 0, 0, 0};

    for (int c = 0; c < NCHUNK; ++c) {
        const int s = c % MSTAGE;
        WAITP(sb + s * 16, fph[s]); fph[s] ^= 1;
        const uint32_t st = sb + MSTAGE0 + s * MSTG_SZ;

        #pragma unroll
        for (int ks = 0; ks < 2; ++ks) {
            uint32_t ah[2][4], al[2][4], bh[6][2];
            #pragma unroll
            for (int t = 0; t < 2; ++t) {
                const uint32_t ao = abase + t * 1024 + ((ks * 32 + akb) ^ aswz);
                ldsm4(ah[t], st + ao);
                ldsm4(al[t], st + 4096 + ao);
            }
            #pragma unroll
            for (int j2 = 0; j2 < 3; ++j2) {
                const uint32_t bo = bbase + j2 * 1024 + ((ks * 32 + bkb) ^ bswz);
                uint32_t r4[4];
                ldsm4(r4, st + 8192 + bo);
                bh[2*j2][0] = r4[0]; bh[2*j2][1] = r4[1];
                bh[2*j2+1][0] = r4[2]; bh[2*j2+1][1] = r4[3];
            }
            #pragma unroll
            for (int t = 0; t < 2; ++t)
                #pragma unroll
                for (int j = 0; j < 6; ++j) {
                    mma_fp16(acc[t][j], ah[t], bh[j]);
                    mma_fp16(acc[t][j], al[t], bh[j]);
                }
        }

        MBAR_ARRIVE(sb + s * 16 + 8);
        if (tid == 0 && c + MSTAGE < NCHUNK) {
            WAITP(sb + s * 16 + 8, eph[s]); eph[s] ^= 1;
            issue_chunk_m(sb, s, f0, c + MSTAGE, &tmXh, &tmXl, &tmW);
        }
    }

    // ---------------- epilogue ----------------
    __syncthreads();
    float* Cs = (float*)(smem + MSTAGE0);   // [192][68]
    const int g  = lane >> 2;
    const int tc = lane & 3;
    #pragma unroll
    for (int t = 0; t < 2; ++t) {
        const int r0 = wm * 32 + t * 16 + g;
        #pragma unroll
        for (int j = 0; j < 6; ++j) {
            const int col = wn * 48 + j * 8 + tc * 2;
            Cs[col * 68 + r0]           = acc[t][j][0];
            Cs[(col + 1) * 68 + r0]     = acc[t][j][1];
            Cs[col * 68 + r0 + 8]       = acc[t][j][2];
            Cs[(col + 1) * 68 + r0 + 8] = acc[t][j][3];
        }
    }
    __syncthreads();
    #pragma unroll
    for (int i = tid; i < NBINS * TILE_M; i += 256) {
        const int bin = i >> 6;
        const int r   = i & 63;
        const int f   = f0 + r;
        if (f < NF) {
            const float re = Cs[bin * 68 + r]           * __ldg(&g_sInv[bin]);
            const float im = Cs[(bin + NBINS) * 68 + r] * __ldg(&g_sInv[bin + NBINS]);
            out[bin * NF + f] = sqrtf(re * re + im * im);
        }
    }

    __syncthreads();
    if (tid == 0) {
        #pragma unroll
        for (int s = 0; s < MSTAGE; s++) { MBAR_INVAL(sb + s * 16); MBAR_INVAL(sb + s * 16 + 8); }
    }
}

// ======================================================================
// host side
// ======================================================================
typedef CUresult (CUDAAPI *EncodeFn)(
    CUtensorMap*, CUtensorMapDataType, cuuint32_t, void*,
    const cuuint64_t*, const cuuint64_t*, const cuuint32_t*, const cuuint32_t*,
    CUtensorMapInterleave, CUtensorMapSwizzle, CUtensorMapL2promotion,
    CUtensorMapFloatOOBfill);

static void encode_2d(EncodeFn enc, CUtensorMap* tm, void* ptr,
                      CUtensorMapDataType dt,
                      unsigned long long d0, unsigned long long d1,
                      unsigned long long strideB,
                      unsigned box0, unsigned box1) {
    cuuint64_t dims[2] = {d0, d1};
    cuuint64_t str[1]  = {strideB};
    cuuint32_t box[2]  = {box0, box1};
    cuuint32_t es[2]   = {1, 1};
    enc(tm, dt, 2, ptr, dims, str, box, es,
        CU_TENSOR_MAP_INTERLEAVE_NONE, CU_TENSOR_MAP_SWIZZLE_64B,
        CU_TENSOR_MAP_L2_PROMOTION_L2_128B, CU_TENSOR_MAP_FLOAT_OOB_FILL_NONE);
}

extern "C" void kernel_launch(void* const* d_in, const int* in_sizes, int n_in,
                              void* d_out, int out_size) {
    const float* x    = (const float*)d_in[0];
    const float* wcos = (const float*)d_in[1];
    const float* wsin = (const float*)d_in[2];
    const float* kr   = (const float*)d_in[3];
    const float* ki   = (const float*)d_in[4];
    float* out = (float*)d_out;

    void* fn = nullptr;
    cudaDriverEntryPointQueryResult st;
#if CUDART_VERSION >= 12050
    cudaGetDriverEntryPointByVersion("cuTensorMapEncodeTiled", &fn, 12000,
                                     cudaEnableDefault, &st);
#else
    cudaGetDriverEntryPoint("cuTensorMapEncodeTiled", &fn, cudaEnableDefault, &st);
#endif
    EncodeFn enc = (EncodeFn)fn;

    void *pxh, *pxl, *pwf, *pah, *pal, *pbh, *pbl;
    cudaGetSymbolAddress(&pxh, g_xh);
    cudaGetSymbolAddress(&pxl, g_xl);
    cudaGetSymbolAddress(&pwf, g_Wf);
    cudaGetSymbolAddress(&pah, g_Ah);
    cudaGetSymbolAddress(&pal, g_Al);
    cudaGetSymbolAddress(&pbh, g_Bh);
    cudaGetSymbolAddress(&pbl, g_Bl);

    CUtensorMap tmXh, tmXl, tmW, tmAh, tmAl, tmBh, tmBl;
    encode_2d(enc, &tmXh, pxh, CU_TENSOR_MAP_DATA_TYPE_FLOAT16,
              512, 16387, 512ull * 2, 32, TILE_M);
    encode_2d(enc, &tmXl, pxl, CU_TENSOR_MAP_DATA_TYPE_FLOAT16,
              512, 16387, 512ull * 2, 32, TILE_M);
    encode_2d(enc, &tmW,  pwf, CU_TENSOR_MAP_DATA_TYPE_FLOAT16,
              FFTLEN, NTC, (unsigned long long)FFTLEN * 2, 32, NTC);
    encode_2d(enc, &tmAh, pah, CU_TENSOR_MAP_DATA_TYPE_BFLOAT16,
              KK, 2048, (unsigned long long)KK * 2, 32, TILE_M);
    encode_2d(enc, &tmAl, pal, CU_TENSOR_MAP_DATA_TYPE_BFLOAT16,
              KK, 2048, (unsigned long long)KK * 2, 32, TILE_M);
    encode_2d(enc, &tmBh, pbh, CU_TENSOR_MAP_DATA_TYPE_BFLOAT16,
              KK, NTC, (unsigned long long)KK * 2, 32, NTC);
    encode_2d(enc, &tmBl, pbl, CU_TENSOR_MAP_DATA_TYPE_BFLOAT16,
              KK, NTC, (unsigned long long)KK * 2, 32, NTC);

    cudaFuncSetAttribute(cqt_mma_kernel,
                         cudaFuncAttributeMaxDynamicSharedMemorySize, MSMEM);
    cudaFuncSetAttribute(comb_mma_kernel,
                         cudaFuncAttributeMaxDynamicSharedMemorySize, CSMEM);

    prep_kernel<<<PREP_BLKS, 256>>>(x, wcos, wsin, kr, ki);
    comb_mma_kernel<<<dim3(32, KSPLIT), 256, CSMEM>>>(tmAh, tmAl, tmBh, tmBl);
    wconvert_kernel<<<NTC, 256>>>();
    cqt_mma_kernel<<<GRID_M, 256, MSMEM>>>(tmXh, tmXl, tmW, out);
}

// round 7
// speedup vs baseline: 7.3110x; 1.4466x over previous
#include <cuda_runtime.h>
#include <cuda_bf16.h>
#include <cuda_fp16.h>
#include <cuda.h>
#include <cstdint>
#include <math.h>

// ---------------- problem constants ----------------
#define NF      16381
#define TS      8388608
#define XPAD    8390144      // 512*16387
#define FFTLEN  2048
#define HOP     512
#define NBINS   84
#define FB      1025
#define NTC     192          // padded N (2*84 -> 192)
#define KC      32
#define NCHUNK  (FFTLEN / KC)   // 64
#define TILE_M  64
#define GRID_M  256

// combine GEMM dims
#define KK      2176
#define KHALF   1088
#define NW      (NTC * FFTLEN)   // 393216
#define KSPLIT  8

typedef unsigned long long ull;
typedef __nv_bfloat16 bf16;
typedef __half fp16;

// ---------------- scratch ----------------
__device__ __align__(16) fp16  g_xh[XPAD];
__device__ __align__(16) fp16  g_Wf[NW];          // fp16 W (unscaled)
__device__ __align__(16) bf16  g_Ah[2048 * KK];
__device__ __align__(16) bf16  g_Al[2048 * KK];
__device__ __align__(16) bf16  g_Bh[NTC * KK];
__device__ __align__(16) bf16  g_Bl[NTC * KK];
__device__ __align__(16) float g_Wpart[KSPLIT * NW];

// ---------------- base-ISA PTX helpers ----------------
__device__ __forceinline__ uint32_t smem_u32(const void* p) {
    uint32_t a;
    asm("{ .reg .u64 t; cvta.to.shared.u64 t, %1; cvt.u32.u64 %0, t; }" : "=r"(a) : "l"(p));
    return a;
}

#define MBAR_INIT(addr, cnt) \
    asm volatile("mbarrier.init.shared.b64 [%0], %1;" :: "r"((uint32_t)(addr)), "r"((uint32_t)(cnt)) : "memory")
#define MBAR_INVAL(addr) \
    asm volatile("mbarrier.inval.shared.b64 [%0];" :: "r"((uint32_t)(addr)) : "memory")
#define MBAR_ARRIVE(addr) \
    asm volatile("mbarrier.arrive.shared.b64 _, [%0];" :: "r"((uint32_t)(addr)) : "memory")
#define MBAR_EXPECT_TX(addr, bytes) \
    asm volatile("mbarrier.arrive.expect_tx.shared.b64 _, [%0], %1;" \
        :: "r"((uint32_t)(addr)), "r"((uint32_t)(bytes)) : "memory")

#define WAITP(mbar, ph) do { \
    uint32_t _m = (uint32_t)(mbar); uint32_t _p = (uint32_t)(ph); uint32_t _d; \
    asm volatile("{\n\t.reg .pred p;\n\t" \
        "mbarrier.try_wait.parity.acquire.cta.shared::cta.b64 p, [%1], %2;\n\t" \
        "selp.b32 %0, 1, 0, p;\n\t}" : "=r"(_d) : "r"(_m), "r"(_p) : "memory"); \
    if (!_d) { \
        asm volatile("{\n\t.reg .pred P1;\n\t" \
            "WL_%=:\n\t" \
            "mbarrier.try_wait.parity.acquire.cta.shared::cta.b64 P1, [%0], %1, 0x989680;\n\t" \
            "@P1 bra.uni WD_%=;\n\t" \
            "bra.uni WL_%=;\n\t" \
            "WD_%=:\n\t}" :: "r"(_m), "r"(_p) : "memory"); \
    } } while (0)

#define TMA2D(dst, map, x0, y0, mb) \
    asm volatile("cp.async.bulk.tensor.2d.shared::cta.global.tile.mbarrier::complete_tx::bytes " \
        "[%0], [%1, {%2, %3}], [%4];" \
        :: "r"((uint32_t)(dst)), "l"(map), "r"((int)(x0)), "r"((int)(y0)), "r"((uint32_t)(mb)) : "memory")

__device__ __forceinline__ void ldsm4(uint32_t* r, uint32_t addr) {
    asm volatile("ldmatrix.sync.aligned.m8n8.x4.shared.b16 {%0,%1,%2,%3}, [%4];"
        : "=r"(r[0]), "=r"(r[1]), "=r"(r[2]), "=r"(r[3]) : "r"(addr));
}
__device__ __forceinline__ void mma_bf16(float* c, const uint32_t* a, const uint32_t* b) {
    asm volatile("mma.sync.aligned.m16n8k16.row.col.f32.bf16.bf16.f32 "
        "{%0,%1,%2,%3}, {%4,%5,%6,%7}, {%8,%9}, {%0,%1,%2,%3};"
        : "+f"(c[0]), "+f"(c[1]), "+f"(c[2]), "+f"(c[3])
        : "r"(a[0]), "r"(a[1]), "r"(a[2]), "r"(a[3]), "r"(b[0]), "r"(b[1]));
}
__device__ __forceinline__ void mma_fp16(float* c, const uint32_t* a, const uint32_t* b) {
    asm volatile("mma.sync.aligned.m16n8k16.row.col.f32.f16.f16.f32 "
        "{%0,%1,%2,%3}, {%4,%5,%6,%7}, {%8,%9}, {%0,%1,%2,%3};"
        : "+f"(c[0]), "+f"(c[1]), "+f"(c[2]), "+f"(c[3])
        : "r"(a[0]), "r"(a[1]), "r"(a[2]), "r"(a[3]), "r"(b[0]), "r"(b[1]));
}

// ======================================================================
// Kernel 1 (merged prep): atrans | bbuild | xconvert in one launch
// ======================================================================
#define ATR_BLKS  4352          // 64 * 68
#define BB_BLKS   1728          // 9 * 192
#define XS_BLKS   8194
#define PREP_BLKS (ATR_BLKS + BB_BLKS + XS_BLKS)

__global__ __launch_bounds__(256) void prep_kernel(
    const float* __restrict__ x,
    const float* __restrict__ wcos, const float* __restrict__ wsin,
    const float* __restrict__ kr,   const float* __restrict__ ki)
{
    __shared__ float t[32][33];
    const int blk = blockIdx.x;
    const int tid = threadIdx.x;

    if (blk < ATR_BLKS) {
        // ---- transpose wcos/wsin -> A' bf16 hi/lo ----
        const int tx = tid & 31, ty = tid >> 5;
        const int m0 = (blk & 63) * 32;
        const int bj = blk >> 6;
        const float* src;
        int srow0, kk0;
        if (bj < 34) { src = wcos; srow0 = bj * 32;        kk0 = bj * 32; }
        else         { src = wsin; srow0 = (bj - 34) * 32; kk0 = KHALF + (bj - 34) * 32; }
        #pragma unroll
        for (int i = 0; i < 4; i++) {
            const int r  = ty + i * 8;
            const int sr = srow0 + r;
            t[r][tx] = (sr < FB) ? src[sr * FFTLEN + m0 + tx] : 0.f;
        }
        __syncthreads();
        #pragma unroll
        for (int i = 0; i < 4; i++) {
            const int m = m0 + ty + i * 8;
            const float v = t[tx][ty + i * 8];
            bf16 h = __float2bfloat16(v);
            g_Ah[m * KK + kk0 + tx] = h;
            g_Al[m * KK + kk0 + tx] = __float2bfloat16(v - __bfloat162float(h));
        }
    } else if (blk < ATR_BLKS + BB_BLKS) {
        // ---- build B' [192, 2176] bf16 hi/lo ----
        const int b2  = blk - ATR_BLKS;
        const int kk  = (b2 % 9) * 256 + tid;
        const int row = b2 / 9;
        if (kk >= KK) return;
        float v = 0.f;
        if (row < NBINS) {
            if (kk < FB)                             v =  kr[row * FB + kk];
            else if (kk >= KHALF && kk < KHALF + FB) v = -ki[row * FB + kk - KHALF];
        } else if (row < 2 * NBINS) {
            const int j = row - NBINS;
            if (kk < FB)                             v =  ki[j * FB + kk];
            else if (kk >= KHALF && kk < KHALF + FB) v =  kr[j * FB + kk - KHALF];
        }
        bf16 h = __float2bfloat16(v);
        g_Bh[row * KK + kk] = h;
        g_Bl[row * KK + kk] = __float2bfloat16(v - __bfloat162float(h));
    } else {
        // ---- x -> fp16, zero pad to XPAD ----
        const int i = ((blk - ATR_BLKS - BB_BLKS) * 256 + tid) * 4;
        if (i >= XPAD) return;
        float v[4];
        if (i + 4 <= TS) {
            float4 q = *(const float4*)(x + i);
            v[0] = q.x; v[1] = q.y; v[2] = q.z; v[3] = q.w;
        } else {
            #pragma unroll
            for (int j = 0; j < 4; j++) v[j] = (i + j < TS) ? x[i + j] : 0.f;
        }
        union { fp16 h[4]; uint2 u; } H;
        #pragma unroll
        for (int j = 0; j < 4; j++) H.h[j] = __float2half(v[j]);
        *(uint2*)&g_xh[i] = H.u;
    }
}

// ======================================================================
// Kernel 2: combine GEMM Wt = A' @ B'^T  (bf16 3-product), K-split x8
// ======================================================================
#define CSTAGE     3
#define CSTG_SZ    32768
#define CSTAGE0    1024
#define CSMEM      (CSTAGE0 + CSTAGE * CSTG_SZ)
#define CCHB       32768

__device__ __forceinline__ void issue_chunk_c(
    uint32_t sb, int s, int m0, int kc,
    const void* tAh, const void* tAl, const void* tBh, const void* tBl)
{
    const uint32_t mb = sb + s * 16;
    const uint32_t st = sb + CSTAGE0 + s * CSTG_SZ;
    MBAR_EXPECT_TX(mb, CCHB);
    TMA2D(st,         tAh, kc * 32, m0, mb);
    TMA2D(st + 4096,  tAl, kc * 32, m0, mb);
    TMA2D(st + 8192,  tBh, kc * 32, 0, mb);
    TMA2D(st + 20480, tBl, kc * 32, 0, mb);
}

__global__ __launch_bounds__(256, 2) void comb_mma_kernel(
    const __grid_constant__ CUtensorMap tmAh,
    const __grid_constant__ CUtensorMap tmAl,
    const __grid_constant__ CUtensorMap tmBh,
    const __grid_constant__ CUtensorMap tmBl)
{
    extern __shared__ __align__(1024) char smem[];
    const uint32_t sb = smem_u32(smem);
    const int tid  = threadIdx.x;
    const int wid  = tid >> 5;
    const int lane = tid & 31;
    const int wm   = wid & 1;
    const int wn   = wid >> 1;
    const int m0   = blockIdx.x * TILE_M;
    const int sp   = blockIdx.y;
    const int nch  = (sp < 4) ? 9 : 8;
    const int ksb  = (sp < 4) ? sp * 9 : 36 + (sp - 4) * 8;

    const int arow  = wm * 32 + (lane & 15);
    const int akb   = (lane >> 4) * 16;
    const int aswz  = ((arow >> 1) & 3) << 4;
    const int abase = arow * 64;
    const int brown = (lane & 7) + ((lane & 16) ? 8 : 0);
    const int bkb   = (lane & 8) ? 16 : 0;
    const int bswz  = ((brown >> 1) & 3) << 4;
    const int bbase = (wn * 48 + brown) * 64;

    if (tid == 0) {
        #pragma unroll
        for (int s = 0; s < CSTAGE; s++) {
            MBAR_INIT(sb + s * 16, 1);
            MBAR_INIT(sb + s * 16 + 8, 256);
        }
    }
    __syncthreads();
    if (tid == 0) {
        #pragma unroll
        for (int s = 0; s < CSTAGE; s++)
            issue_chunk_c(sb, s, m0, ksb + s, &tmAh, &tmAl, &tmBh, &tmBl);
    }

    float acc[2][6][4];
    #pragma unroll
    for (int t = 0; t < 2; t++)
        #pragma unroll
        for (int j = 0; j < 6; j++)
            #pragma unroll
            for (int q = 0; q < 4; q++) acc[t][j][q] = 0.f;

    int fph[CSTAGE] = {0, 0, 0};
    int eph[CSTAGE] = {0, 0, 0};

    for (int c = 0; c < nch; ++c) {
        const int s = c % CSTAGE;
        WAITP(sb + s * 16, fph[s]); fph[s] ^= 1;
        const uint32_t st = sb + CSTAGE0 + s * CSTG_SZ;

        #pragma unroll
        for (int ks = 0; ks < 2; ++ks) {
            uint32_t ah[2][4], alr[2][4], bh[6][2], blr[6][2];
            #pragma unroll
            for (int t = 0; t < 2; ++t) {
                const uint32_t ao = abase + t * 1024 + ((ks * 32 + akb) ^ aswz);
                ldsm4(ah[t],  st + ao);
                ldsm4(alr[t], st + 4096 + ao);
            }
            #pragma unroll
            for (int j2 = 0; j2 < 3; ++j2) {
                const uint32_t bo = bbase + j2 * 1024 + ((ks * 32 + bkb) ^ bswz);
                uint32_t r4[4];
                ldsm4(r4, st + 8192 + bo);
                bh[2*j2][0] = r4[0]; bh[2*j2][1] = r4[1];
                bh[2*j2+1][0] = r4[2]; bh[2*j2+1][1] = r4[3];
                ldsm4(r4, st + 20480 + bo);
                blr[2*j2][0] = r4[0]; blr[2*j2][1] = r4[1];
                blr[2*j2+1][0] = r4[2]; blr[2*j2+1][1] = r4[3];
            }
            #pragma unroll
            for (int t = 0; t < 2; ++t)
                #pragma unroll
                for (int j = 0; j < 6; ++j) {
                    mma_bf16(acc[t][j], ah[t],  bh[j]);
                    mma_bf16(acc[t][j], ah[t],  blr[j]);
                    mma_bf16(acc[t][j], alr[t], bh[j]);
                }
        }

        MBAR_ARRIVE(sb + s * 16 + 8);
        if (tid == 0 && c + CSTAGE < nch) {
            WAITP(sb + s * 16 + 8, eph[s]); eph[s] ^= 1;
            issue_chunk_c(sb, s, m0, ksb + c + CSTAGE, &tmAh, &tmAl, &tmBh, &tmBl);
        }
    }

    __syncthreads();
    float* Cs = (float*)(smem + CSTAGE0);   // [192][68]
    const int g  = lane >> 2;
    const int tc = lane & 3;
    #pragma unroll
    for (int t = 0; t < 2; ++t) {
        const int r0 = wm * 32 + t * 16 + g;
        #pragma unroll
        for (int j = 0; j < 6; ++j) {
            const int col = wn * 48 + j * 8 + tc * 2;
            Cs[col * 68 + r0]           = acc[t][j][0];
            Cs[(col + 1) * 68 + r0]     = acc[t][j][1];
            Cs[col * 68 + r0 + 8]       = acc[t][j][2];
            Cs[(col + 1) * 68 + r0 + 8] = acc[t][j][3];
        }
    }
    __syncthreads();
    float* dst = g_Wpart + sp * NW;
    #pragma unroll
    for (int i = tid; i < NTC * TILE_M; i += 256) {
        const int bin = i >> 6;
        const int r   = i & 63;
        dst[bin * FFTLEN + m0 + r] = Cs[bin * 68 + r];
    }

    __syncthreads();
    if (tid == 0) {
        #pragma unroll
        for (int s = 0; s < CSTAGE; s++) { MBAR_INVAL(sb + s * 16); MBAR_INVAL(sb + s * 16 + 8); }
    }
}

// ======================================================================
// Kernel 3: reduce 8 partials -> fp16 W (no scaling; fp16 err is relative)
// ======================================================================
__global__ __launch_bounds__(256) void wconvert_kernel() {
    const int i = (blockIdx.x * 256 + threadIdx.x) * 4;
    if (i >= NW) return;
    float4 s = *(const float4*)&g_Wpart[i];
    #pragma unroll
    for (int p = 1; p < KSPLIT; p++) {
        float4 q = *(const float4*)&g_Wpart[p * NW + i];
        s.x += q.x; s.y += q.y; s.z += q.z; s.w += q.w;
    }
    union { fp16 h[4]; uint2 u; } H;
    H.h[0] = __float2half(s.x); H.h[1] = __float2half(s.y);
    H.h[2] = __float2half(s.z); H.h[3] = __float2half(s.w);
    *(uint2*)&g_Wf[i] = H.u;
}

// ======================================================================
// Kernel 4: main fp16 GEMM (single product) + magnitude epilogue
//   stage: A 4KB | B 12KB = 16KB, 6 stages, 2 CTAs/SM
// ======================================================================
#define MSTAGE   6
#define MSTG_SZ  16384
#define MSTAGE0  1024
#define MSMEM    (MSTAGE0 + MSTAGE * MSTG_SZ)   // 99328
#define MCHB     16384

__device__ __forceinline__ void issue_chunk_m(
    uint32_t sb, int s, int f0, int c,
    const void* tX, const void* tW)
{
    const uint32_t mb = sb + s * 16;
    const uint32_t st = sb + MSTAGE0 + s * MSTG_SZ;
    const int kx = (c & 15) * 32;
    const int ky = f0 + (c >> 4);
    MBAR_EXPECT_TX(mb, MCHB);
    TMA2D(st,        tX, kx, ky, mb);
    TMA2D(st + 4096, tW, c * 32, 0, mb);
}

__global__ __launch_bounds__(256, 2) void cqt_mma_kernel(
    const __grid_constant__ CUtensorMap tmX,
    const __grid_constant__ CUtensorMap tmW,
    float* __restrict__ out)
{
    extern __shared__ __align__(1024) char smem[];
    const uint32_t sb = smem_u32(smem);
    const int tid  = threadIdx.x;
    const int wid  = tid >> 5;
    const int lane = tid & 31;
    const int wm   = wid & 1;
    const int wn   = wid >> 1;
    const int f0   = blockIdx.x * TILE_M;

    const int arow  = wm * 32 + (lane & 15);
    const int akb   = (lane >> 4) * 16;
    const int aswz  = ((arow >> 1) & 3) << 4;
    const int abase = arow * 64;
    const int brown = (lane & 7) + ((lane & 16) ? 8 : 0);
    const int bkb   = (lane & 8) ? 16 : 0;
    const int bswz  = ((brown >> 1) & 3) << 4;
    const int bbase = (wn * 48 + brown) * 64;

    if (tid == 0) {
        #pragma unroll
        for (int s = 0; s < MSTAGE; s++) {
            MBAR_INIT(sb + s * 16, 1);
            MBAR_INIT(sb + s * 16 + 8, 256);
        }
    }
    __syncthreads();
    if (tid == 0) {
        #pragma unroll
        for (int s = 0; s < MSTAGE; s++)
            issue_chunk_m(sb, s, f0, s, &tmX, &tmW);
    }

    float acc[2][6][4];
    #pragma unroll
    for (int t = 0; t < 2; t++)
        #pragma unroll
        for (int j = 0; j < 6; j++)
            #pragma unroll
            for (int q = 0; q < 4; q++) acc[t][j][q] = 0.f;

    int fph[MSTAGE] = {0, 0, 0, 0, 0, 0};
    int eph[MSTAGE] = {0, 0, 0, 0, 0, 0};

    for (int c = 0; c < NCHUNK; ++c) {
        const int s = c % MSTAGE;
        WAITP(sb + s * 16, fph[s]); fph[s] ^= 1;
        const uint32_t st = sb + MSTAGE0 + s * MSTG_SZ;

        #pragma unroll
        for (int ks = 0; ks < 2; ++ks) {
            uint32_t ah[2][4], bh[6][2];
            #pragma unroll
            for (int t = 0; t < 2; ++t) {
                const uint32_t ao = abase + t * 1024 + ((ks * 32 + akb) ^ aswz);
                ldsm4(ah[t], st + ao);
            }
            #pragma unroll
            for (int j2 = 0; j2 < 3; ++j2) {
                const uint32_t bo = bbase + j2 * 1024 + ((ks * 32 + bkb) ^ bswz);
                uint32_t r4[4];
                ldsm4(r4, st + 4096 + bo);
                bh[2*j2][0] = r4[0]; bh[2*j2][1] = r4[1];
                bh[2*j2+1][0] = r4[2]; bh[2*j2+1][1] = r4[3];
            }
            #pragma unroll
            for (int t = 0; t < 2; ++t)
                #pragma unroll
                for (int j = 0; j < 6; ++j)
                    mma_fp16(acc[t][j], ah[t], bh[j]);
        }

        MBAR_ARRIVE(sb + s * 16 + 8);
        if (tid == 0 && c + MSTAGE < NCHUNK) {
            WAITP(sb + s * 16 + 8, eph[s]); eph[s] ^= 1;
            issue_chunk_m(sb, s, f0, c + MSTAGE, &tmX, &tmW);
        }
    }

    // ---------------- epilogue ----------------
    __syncthreads();
    float* Cs = (float*)(smem + MSTAGE0);   // [192][68]
    const int g  = lane >> 2;
    const int tc = lane & 3;
    #pragma unroll
    for (int t = 0; t < 2; ++t) {
        const int r0 = wm * 32 + t * 16 + g;
        #pragma unroll
        for (int j = 0; j < 6; ++j) {
            const int col = wn * 48 + j * 8 + tc * 2;
            Cs[col * 68 + r0]           = acc[t][j][0];
            Cs[(col + 1) * 68 + r0]     = acc[t][j][1];
            Cs[col * 68 + r0 + 8]       = acc[t][j][2];
            Cs[(col + 1) * 68 + r0 + 8] = acc[t][j][3];
        }
    }
    __syncthreads();
    #pragma unroll
    for (int i = tid; i < NBINS * TILE_M; i += 256) {
        const int bin = i >> 6;
        const int r   = i & 63;
        const int f   = f0 + r;
        if (f < NF) {
            const float re = Cs[bin * 68 + r];
            const float im = Cs[(bin + NBINS) * 68 + r];
            out[bin * NF + f] = sqrtf(re * re + im * im);
        }
    }

    __syncthreads();
    if (tid == 0) {
        #pragma unroll
        for (int s = 0; s < MSTAGE; s++) { MBAR_INVAL(sb + s * 16); MBAR_INVAL(sb + s * 16 + 8); }
    }
}

// ======================================================================
// host side
// ======================================================================
typedef CUresult (CUDAAPI *EncodeFn)(
    CUtensorMap*, CUtensorMapDataType, cuuint32_t, void*,
    const cuuint64_t*, const cuuint64_t*, const cuuint32_t*, const cuuint32_t*,
    CUtensorMapInterleave, CUtensorMapSwizzle, CUtensorMapL2promotion,
    CUtensorMapFloatOOBfill);

static void encode_2d(EncodeFn enc, CUtensorMap* tm, void* ptr,
                      CUtensorMapDataType dt,
                      unsigned long long d0, unsigned long long d1,
                      unsigned long long strideB,
                      unsigned box0, unsigned box1) {
    cuuint64_t dims[2] = {d0, d1};
    cuuint64_t str[1]  = {strideB};
    cuuint32_t box[2]  = {box0, box1};
    cuuint32_t es[2]   = {1, 1};
    enc(tm, dt, 2, ptr, dims, str, box, es,
        CU_TENSOR_MAP_INTERLEAVE_NONE, CU_TENSOR_MAP_SWIZZLE_64B,
        CU_TENSOR_MAP_L2_PROMOTION_L2_128B, CU_TENSOR_MAP_FLOAT_OOB_FILL_NONE);
}

extern "C" void kernel_launch(void* const* d_in, const int* in_sizes, int n_in,
                              void* d_out, int out_size) {
    const float* x    = (const float*)d_in[0];
    const float* wcos = (const float*)d_in[1];
    const float* wsin = (const float*)d_in[2];
    const float* kr   = (const float*)d_in[3];
    const float* ki   = (const float*)d_in[4];
    float* out = (float*)d_out;

    void* fn = nullptr;
    cudaDriverEntryPointQueryResult st;
#if CUDART_VERSION >= 12050
    cudaGetDriverEntryPointByVersion("cuTensorMapEncodeTiled", &fn, 12000,
                                     cudaEnableDefault, &st);
#else
    cudaGetDriverEntryPoint("cuTensorMapEncodeTiled", &fn, cudaEnableDefault, &st);
#endif
    EncodeFn enc = (EncodeFn)fn;

    void *pxh, *pwf, *pah, *pal, *pbh, *pbl;
    cudaGetSymbolAddress(&pxh, g_xh);
    cudaGetSymbolAddress(&pwf, g_Wf);
    cudaGetSymbolAddress(&pah, g_Ah);
    cudaGetSymbolAddress(&pal, g_Al);
    cudaGetSymbolAddress(&pbh, g_Bh);
    cudaGetSymbolAddress(&pbl, g_Bl);

    CUtensorMap tmX, tmW, tmAh, tmAl, tmBh, tmBl;
    encode_2d(enc, &tmX, pxh, CU_TENSOR_MAP_DATA_TYPE_FLOAT16,
              512, 16387, 512ull * 2, 32, TILE_M);
    encode_2d(enc, &tmW, pwf, CU_TENSOR_MAP_DATA_TYPE_FLOAT16,
              FFTLEN, NTC, (unsigned long long)FFTLEN * 2, 32, NTC);
    encode_2d(enc, &tmAh, pah, CU_TENSOR_MAP_DATA_TYPE_BFLOAT16,
              KK, 2048, (unsigned long long)KK * 2, 32, TILE_M);
    encode_2d(enc, &tmAl, pal, CU_TENSOR_MAP_DATA_TYPE_BFLOAT16,
              KK, 2048, (unsigned long long)KK * 2, 32, TILE_M);
    encode_2d(enc, &tmBh, pbh, CU_TENSOR_MAP_DATA_TYPE_BFLOAT16,
              KK, NTC, (unsigned long long)KK * 2, 32, NTC);
    encode_2d(enc, &tmBl, pbl, CU_TENSOR_MAP_DATA_TYPE_BFLOAT16,
              KK, NTC, (unsigned long long)KK * 2, 32, NTC);

    cudaFuncSetAttribute(cqt_mma_kernel,
                         cudaFuncAttributeMaxDynamicSharedMemorySize, MSMEM);
    cudaFuncSetAttribute(comb_mma_kernel,
                         cudaFuncAttributeMaxDynamicSharedMemorySize, CSMEM);

    prep_kernel<<<PREP_BLKS, 256>>>(x, wcos, wsin, kr, ki);
    comb_mma_kernel<<<dim3(32, KSPLIT), 256, CSMEM>>>(tmAh, tmAl, tmBh, tmBl);
    wconvert_kernel<<<NW / 1024, 256>>>();
    cqt_mma_kernel<<<GRID_M, 256, MSMEM>>>(tmX, tmW, out);
}